// round 1
// baseline (speedup 1.0000x reference)
#include <cuda_runtime.h>
#include <cstdint>

#define H 128
#define NBUCKETS 9     // 8 expert buckets + 1 passthrough (sel out of range)
#define TILE_M 128
#define THREADS 256

// ---------------- device scratch (static allocation: allowed) ----------------
__device__ float4 g_accum4[100000 * (H / 4)];   // node accumulator [N][128], 51.2 MB
__device__ int    g_perm[1000000];              // bucket-sorted edge permutation
__device__ int    g_hist[16];
__device__ int    g_start[NBUCKETS];
__device__ int    g_count[NBUCKETS];
__device__ int    g_cursor[NBUCKETS];
__device__ int    g_tileOff[NBUCKETS + 1];

// ---------------- helpers ----------------
__device__ __forceinline__ int bucket_of(float d) {
    // exact replica of reference op order: sub, div, mul(by 8 == exact), floor
    float t = (d - 0.8f) / 5.0001f * 8.0f;
    float f = floorf(t);
    return (f >= 0.0f && f < 8.0f) ? (int)f : 8;   // out-of-range -> passthrough
}

__device__ __forceinline__ void red_add_v4(float* p, float a, float b, float c, float d) {
    asm volatile("red.global.add.v4.f32 [%0], {%1,%2,%3,%4};"
                 :: "l"(p), "f"(a), "f"(b), "f"(c), "f"(d) : "memory");
}

// ---------------- kernel 1: zero accumulator + histogram init ----------------
__global__ void k_zero(int n4) {
    int i = blockIdx.x * blockDim.x + threadIdx.x;
    int stride = gridDim.x * blockDim.x;
    float4 z = make_float4(0.f, 0.f, 0.f, 0.f);
    for (; i < n4; i += stride) g_accum4[i] = z;
    if (blockIdx.x == 0 && threadIdx.x < 16) g_hist[threadIdx.x] = 0;
}

// ---------------- kernel 2: bucket histogram ----------------
__global__ void k_hist(const float* __restrict__ dist, int E) {
    __shared__ int lh[NBUCKETS];
    if (threadIdx.x < NBUCKETS) lh[threadIdx.x] = 0;
    __syncthreads();
    int i = blockIdx.x * blockDim.x + threadIdx.x;
    int stride = gridDim.x * blockDim.x;
    for (; i < E; i += stride) atomicAdd(&lh[bucket_of(dist[i])], 1);
    __syncthreads();
    if (threadIdx.x < NBUCKETS) atomicAdd(&g_hist[threadIdx.x], lh[threadIdx.x]);
}

// ---------------- kernel 3: tiny scan ----------------
__global__ void k_scan() {
    if (threadIdx.x == 0 && blockIdx.x == 0) {
        int off = 0, toff = 0;
        for (int s = 0; s < NBUCKETS; s++) {
            int c = g_hist[s];
            g_start[s]  = off;
            g_cursor[s] = off;
            g_count[s]  = c;
            g_tileOff[s] = toff;
            off  += c;
            toff += (c + TILE_M - 1) / TILE_M;
        }
        g_tileOff[NBUCKETS] = toff;
    }
}

// ---------------- kernel 4: warp-aggregated scatter (counting sort) ----------------
__global__ void k_scatter(const float* __restrict__ dist, int E) {
    int lane = threadIdx.x & 31;
    unsigned ltmask = (1u << lane) - 1u;
    int i = blockIdx.x * blockDim.x + threadIdx.x;
    int stride = gridDim.x * blockDim.x;
    // E and stride are multiples of 32 -> every executing warp is full
    for (; i < E; i += stride) {
        int s = bucket_of(dist[i]);
        int pos = 0;
        #pragma unroll
        for (int s0 = 0; s0 < NBUCKETS; s0++) {
            unsigned m = __ballot_sync(0xffffffffu, s == s0);
            if (s == s0) {
                int leader = __ffs(m) - 1;
                int base = 0;
                if (lane == leader) base = atomicAdd(&g_cursor[s0], __popc(m));
                base = __shfl_sync(m, base, leader);
                pos = base + __popc(m & ltmask);
            }
        }
        g_perm[pos] = i;
    }
}

// ---------------- kernel 5: edge expert GEMM + scatter-add ----------------
// dynamic smem layout (floats)
#define OFF_W   0                         // sW[k][j]     128*128
#define OFF_H   16384                     // sH[r][132]   padded against conflicts
#define OFF_RBF (OFF_H + 128 * 132)       // sRbf[r*6+q]
#define OFF_WT  (OFF_RBF + 768)           // sWT[q*128+c] (w_rbf transposed)
#define OFF_INT (OFF_WT + 768)            // sPerm[128], sNode[128]
#define EDGE_SMEM_FLOATS (OFF_INT + 256 + 8)
#define EDGE_SMEM_BYTES  (EDGE_SMEM_FLOATS * 4)

__global__ void __launch_bounds__(THREADS, 1)
k_edge(const float* __restrict__ x, const float* __restrict__ rbf,
       const int* __restrict__ eidx, const float* __restrict__ w_rbf,
       const float* __restrict__ sel_w)
{
    extern __shared__ float sm[];
    float* sW   = sm + OFF_W;
    float* sH   = sm + OFF_H;
    float* sRbf = sm + OFF_RBF;
    float* sWT  = sm + OFF_WT;
    int*   sPerm = (int*)(sm + OFF_INT);
    int*   sNode = sPerm + 128;
    __shared__ int sS, sRows, sBase;

    int t = threadIdx.x;
    if (t == 0) {
        int b = blockIdx.x;
        int found = -1, t0s = 0;
        #pragma unroll
        for (int q = 0; q < NBUCKETS; q++) {
            if (b >= g_tileOff[q] && b < g_tileOff[q + 1]) { found = q; t0s = g_tileOff[q]; }
        }
        if (found < 0) { sS = -1; sRows = 0; sBase = 0; }
        else {
            int rowBase = (b - t0s) * TILE_M;
            sS = found;
            sRows = min(TILE_M, g_count[found] - rowBase);
            sBase = g_start[found] + rowBase;
        }
    }
    __syncthreads();
    int s = sS, rows = sRows, base = sBase;
    if (s < 0) return;

    if (t < TILE_M) {
        int pe = (t < rows) ? g_perm[base + t] : 0;
        sPerm[t] = pe;
        sNode[t] = eidx[pe];
    }
    for (int idx = t; idx < 768; idx += THREADS) {          // transpose w_rbf
        int q = idx >> 7, c = idx & 127;
        sWT[idx] = w_rbf[c * 6 + q];
    }
    __syncthreads();
    for (int idx = t; idx < rows * 6; idx += THREADS) {     // gather rbf rows
        int r = idx / 6;
        sRbf[idx] = rbf[(size_t)sPerm[r] * 6 + (idx - r * 6)];
    }
    if (s < 8) {                                            // load expert weight
        const float4* Wg = (const float4*)(sel_w + (size_t)s * (H * H));
        float4* Ws = (float4*)sW;
        for (int idx = t; idx < H * H / 4; idx += THREADS) Ws[idx] = Wg[idx];
    }
    __syncthreads();

    // build h = (rbf @ w_rbf^T) * x for this tile
    int wa = t >> 5, lane = t & 31;
    int c0 = lane * 4;
    #pragma unroll 4
    for (int r = wa; r < TILE_M; r += 8) {
        bool act = (r < rows);
        int pe = sPerm[r];
        float4 g = make_float4(0.f, 0.f, 0.f, 0.f);
        #pragma unroll
        for (int q = 0; q < 6; q++) {
            float rq = sRbf[r * 6 + q];
            float4 wq = *(float4*)&sWT[q * 128 + c0];
            g.x += rq * wq.x; g.y += rq * wq.y; g.z += rq * wq.z; g.w += rq * wq.w;
        }
        float4 xv = *(const float4*)&x[(size_t)pe * H + c0];
        float4 h;
        h.x = act ? g.x * xv.x : 0.f;
        h.y = act ? g.y * xv.y : 0.f;
        h.z = act ? g.z * xv.z : 0.f;
        h.w = act ? g.w * xv.w : 0.f;
        *(float4*)&sH[r * 132 + c0] = h;
    }
    __syncthreads();

    int tc = t & 15, tr = t >> 4;   // thread owns rows tr+16m, cols tc*8+jj
    if (s < 8) {
        float acc[8][8];
        #pragma unroll
        for (int m = 0; m < 8; m++)
            #pragma unroll
            for (int j = 0; j < 8; j++) acc[m][j] = 0.f;

        #pragma unroll 1
        for (int k4 = 0; k4 < 32; k4++) {
            float4 a[8];
            #pragma unroll
            for (int m = 0; m < 8; m++)
                a[m] = *(float4*)&sH[(tr + 16 * m) * 132 + k4 * 4];
            #pragma unroll
            for (int kk = 0; kk < 4; kk++) {
                const float* wrow = &sW[(k4 * 4 + kk) * 128 + tc * 8];
                float4 w0 = *(float4*)wrow;
                float4 w1 = *(float4*)(wrow + 4);
                #pragma unroll
                for (int m = 0; m < 8; m++) {
                    float av = (kk == 0) ? a[m].x : (kk == 1) ? a[m].y
                             : (kk == 2) ? a[m].z : a[m].w;
                    acc[m][0] += av * w0.x; acc[m][1] += av * w0.y;
                    acc[m][2] += av * w0.z; acc[m][3] += av * w0.w;
                    acc[m][4] += av * w1.x; acc[m][5] += av * w1.y;
                    acc[m][6] += av * w1.z; acc[m][7] += av * w1.w;
                }
            }
        }
        #pragma unroll
        for (int m = 0; m < 8; m++) {
            int r = tr + 16 * m;
            if (r < rows) {
                float* dst = (float*)g_accum4 + (size_t)sNode[r] * H + tc * 8;
                red_add_v4(dst,     acc[m][0], acc[m][1], acc[m][2], acc[m][3]);
                red_add_v4(dst + 4, acc[m][4], acc[m][5], acc[m][6], acc[m][7]);
            }
        }
    } else {  // passthrough bucket: scatter h directly
        #pragma unroll
        for (int m = 0; m < 8; m++) {
            int r = tr + 16 * m;
            if (r < rows) {
                float4 v0 = *(float4*)&sH[r * 132 + tc * 8];
                float4 v1 = *(float4*)&sH[r * 132 + tc * 8 + 4];
                float* dst = (float*)g_accum4 + (size_t)sNode[r] * H + tc * 8;
                red_add_v4(dst,     v0.x, v0.y, v0.z, v0.w);
                red_add_v4(dst + 4, v1.x, v1.y, v1.z, v1.w);
            }
        }
    }
}

// ---------------- kernel 6: fused node MLP (3x SiLU + out proj) ----------------
#define MOFF_IN 0
#define MOFF_W  (128 * 132)
#define MOFF_B  (MOFF_W + 128 * 132)
#define MLP_SMEM_FLOATS (MOFF_B + 128)
#define MLP_SMEM_BYTES  (MLP_SMEM_FLOATS * 4)

__global__ void __launch_bounds__(THREADS, 1)
k_mlp(const float* __restrict__ w1, const float* __restrict__ b1,
      const float* __restrict__ w2, const float* __restrict__ b2,
      const float* __restrict__ w3, const float* __restrict__ b3,
      const float* __restrict__ wout, float* __restrict__ out, int N)
{
    extern __shared__ float sm[];
    float* sIn = sm + MOFF_IN;
    float* sW  = sm + MOFF_W;
    float* sB  = sm + MOFF_B;
    int t = threadIdx.x;
    int nb = blockIdx.x * 128;
    int rows = min(128, N - nb);

    const float* accum = (const float*)g_accum4;
    for (int idx = t * 4; idx < 128 * 128; idx += THREADS * 4) {
        int r = idx >> 7, c = idx & 127;
        float4 v = (r < rows) ? *(const float4*)&accum[(size_t)(nb + r) * H + c]
                              : make_float4(0.f, 0.f, 0.f, 0.f);
        *(float4*)&sIn[r * 132 + c] = v;
    }

    const float* Ws[4] = {w1, w2, w3, wout};
    const float* Bs[3] = {b1, b2, b3};
    int tc = t & 15, tr = t >> 4;   // rows tr+16m, cols tc+16jj

    for (int l = 0; l < 4; l++) {
        __syncthreads();
        for (int idx = t * 4; idx < 128 * 128; idx += THREADS * 4) {
            int r = idx >> 7, c = idx & 127;
            *(float4*)&sW[r * 132 + c] = *(const float4*)&Ws[l][idx];
        }
        if (l < 3 && t < 128) sB[t] = Bs[l][t];
        __syncthreads();

        float acc[8][8];
        #pragma unroll
        for (int m = 0; m < 8; m++)
            #pragma unroll
            for (int j = 0; j < 8; j++) acc[m][j] = 0.f;

        #pragma unroll 1
        for (int k4 = 0; k4 < 32; k4++) {
            float4 a[8], w[8];
            #pragma unroll
            for (int m = 0; m < 8; m++)
                a[m] = *(float4*)&sIn[(tr + 16 * m) * 132 + k4 * 4];
            #pragma unroll
            for (int j = 0; j < 8; j++)
                w[j] = *(float4*)&sW[(tc + 16 * j) * 132 + k4 * 4];
            #pragma unroll
            for (int m = 0; m < 8; m++)
                #pragma unroll
                for (int j = 0; j < 8; j++)
                    acc[m][j] += a[m].x * w[j].x + a[m].y * w[j].y
                               + a[m].z * w[j].z + a[m].w * w[j].w;
        }

        if (l < 3) {
            __syncthreads();   // all sIn reads done before overwrite
            #pragma unroll
            for (int m = 0; m < 8; m++)
                #pragma unroll
                for (int j = 0; j < 8; j++) {
                    float v = acc[m][j] + sB[tc + 16 * j];
                    float sg = 1.0f / (1.0f + __expf(-v));
                    sIn[(tr + 16 * m) * 132 + (tc + 16 * j)] = v * sg;
                }
        } else {
            #pragma unroll
            for (int m = 0; m < 8; m++) {
                int r = tr + 16 * m;
                if (nb + r < N) {
                    #pragma unroll
                    for (int j = 0; j < 8; j++)
                        out[(size_t)(nb + r) * H + tc + 16 * j] = acc[m][j];
                }
            }
        }
    }
}

// ---------------- launcher ----------------
extern "C" void kernel_launch(void* const* d_in, const int* in_sizes, int n_in,
                              void* d_out, int out_size)
{
    const float* x    = (const float*)d_in[0];
    const float* rbf  = (const float*)d_in[1];
    const int*   ei   = (const int*)  d_in[2];
    const float* dist = (const float*)d_in[3];
    // locate w_rbf by its unique size (768) — num_nodes scalar may or may not be materialized
    int k = 4;
    while (k < n_in && in_sizes[k] != 768) k++;
    const float* w_rbf = (const float*)d_in[k];
    const float* sel_w = (const float*)d_in[k + 1];
    const float* w1    = (const float*)d_in[k + 2];
    const float* b1    = (const float*)d_in[k + 3];
    const float* w2    = (const float*)d_in[k + 4];
    const float* b2    = (const float*)d_in[k + 5];
    const float* w3    = (const float*)d_in[k + 6];
    const float* b3    = (const float*)d_in[k + 7];
    const float* wout  = (const float*)d_in[k + 8];

    int E = in_sizes[0] / H;
    int N = out_size / H;

    cudaFuncSetAttribute(k_edge, cudaFuncAttributeMaxDynamicSharedMemorySize, EDGE_SMEM_BYTES);
    cudaFuncSetAttribute(k_mlp,  cudaFuncAttributeMaxDynamicSharedMemorySize, MLP_SMEM_BYTES);

    k_zero<<<512, 256>>>(N * (H / 4));
    k_hist<<<1024, 256>>>(dist, E);
    k_scan<<<1, 1>>>();
    k_scatter<<<1024, 256>>>(dist, E);

    int tiles = (E + TILE_M - 1) / TILE_M + NBUCKETS;
    k_edge<<<tiles, THREADS, EDGE_SMEM_BYTES>>>(x, rbf, ei, w_rbf, sel_w);
    k_mlp<<<(N + 127) / 128, THREADS, MLP_SMEM_BYTES>>>(w1, b1, w2, b2, w3, b3, wout,
                                                        (float*)d_out, N);
}

// round 3
// speedup vs baseline: 1.4409x; 1.4409x over previous
#include <cuda_runtime.h>
#include <cuda_bf16.h>
#include <cstdint>

#define H 128
#define NBUCKETS 9     // 8 expert buckets + 1 passthrough
#define TILE_M 128
#define THREADS 256

// row stride for bf16 operand tiles: 136 elems = 272B = 17*16B (odd -> ldmatrix conflict-free)
#define RSTRIDE_E 136
#define RSTRIDE_B 272

// ---------------- device scratch ----------------
__device__ float4 g_accum4[100000 * (H / 4)];   // node accumulator [N][128]
__device__ int    g_perm[1000000];
__device__ int    g_hist[16];
__device__ int    g_start[NBUCKETS];
__device__ int    g_count[NBUCKETS];
__device__ int    g_cursor[NBUCKETS];
__device__ int    g_tileOff[NBUCKETS + 1];
// pre-split weights, slot 0..7 = experts (transposed to B^T[n][k]=W[k][n]),
// slot 8..11 = MLP w1,w2,w3,wout (already [n][k])
__device__ __align__(16) __nv_bfloat16 g_wsp_hi[12][128][RSTRIDE_E];
__device__ __align__(16) __nv_bfloat16 g_wsp_lo[12][128][RSTRIDE_E];

// ---------------- helpers ----------------
__device__ __forceinline__ int bucket_of(float d) {
    float t = (d - 0.8f) / 5.0001f * 8.0f;
    float f = floorf(t);
    return (f >= 0.0f && f < 8.0f) ? (int)f : 8;
}

__device__ __forceinline__ void red_add_v4(float* p, float a, float b, float c, float d) {
    asm volatile("red.global.add.v4.f32 [%0], {%1,%2,%3,%4};"
                 :: "l"(p), "f"(a), "f"(b), "f"(c), "f"(d) : "memory");
}
__device__ __forceinline__ void red_add_v2(float* p, float a, float b) {
    asm volatile("red.global.add.v2.f32 [%0], {%1,%2};"
                 :: "l"(p), "f"(a), "f"(b) : "memory");
}

__device__ __forceinline__ uint32_t smem_u32(const void* p) {
    uint32_t a;
    asm("{ .reg .u64 t; cvta.to.shared.u64 t, %1; cvt.u32.u64 %0, t; }" : "=r"(a) : "l"(p));
    return a;
}

__device__ __forceinline__ void ldsm_x4(uint32_t& r0, uint32_t& r1, uint32_t& r2, uint32_t& r3,
                                        uint32_t addr) {
    asm volatile("ldmatrix.sync.aligned.m8n8.x4.shared.b16 {%0,%1,%2,%3}, [%4];"
                 : "=r"(r0), "=r"(r1), "=r"(r2), "=r"(r3) : "r"(addr));
}

__device__ __forceinline__ void mma_bf16(float* d, uint32_t a0, uint32_t a1, uint32_t a2,
                                         uint32_t a3, uint32_t b0, uint32_t b1) {
    asm volatile("mma.sync.aligned.m16n8k16.row.col.f32.bf16.bf16.f32 "
                 "{%0,%1,%2,%3}, {%4,%5,%6,%7}, {%8,%9}, {%0,%1,%2,%3};"
                 : "+f"(d[0]), "+f"(d[1]), "+f"(d[2]), "+f"(d[3])
                 : "r"(a0), "r"(a1), "r"(a2), "r"(a3), "r"(b0), "r"(b1));
}

// pack two floats into hi-bf16 pair (return) and lo-bf16 pair (out param)
__device__ __forceinline__ uint32_t split2(float v0, float v1, uint32_t& lo) {
    __nv_bfloat16 h0 = __float2bfloat16_rn(v0), h1 = __float2bfloat16_rn(v1);
    __nv_bfloat16 l0 = __float2bfloat16_rn(v0 - __bfloat162float(h0));
    __nv_bfloat16 l1 = __float2bfloat16_rn(v1 - __bfloat162float(h1));
    lo = (uint32_t)__bfloat16_as_ushort(l0) | ((uint32_t)__bfloat16_as_ushort(l1) << 16);
    return (uint32_t)__bfloat16_as_ushort(h0) | ((uint32_t)__bfloat16_as_ushort(h1) << 16);
}

// one split-product pass: acc[16][4] += A(16x128 stripe at m0) * B^T  (both bf16, stride 272B)
__device__ __forceinline__ void mma_stripe(float (*acc)[4], uint32_t aBase, uint32_t bBase,
                                           int lane, int m0) {
    uint32_t aAddr = aBase + (uint32_t)(m0 + (lane & 15)) * RSTRIDE_B
                   + (uint32_t)((lane >> 4) << 4);
    uint32_t bAddr = bBase + (uint32_t)((lane & 7) + ((lane >> 4) << 3)) * RSTRIDE_B
                   + (uint32_t)(((lane >> 3) & 1) << 4);
    #pragma unroll
    for (int k0 = 0; k0 < 8; k0++) {
        uint32_t a0, a1, a2, a3;
        ldsm_x4(a0, a1, a2, a3, aAddr + k0 * 32);
        #pragma unroll
        for (int j2 = 0; j2 < 8; j2++) {
            uint32_t b0, b1, b2, b3;
            ldsm_x4(b0, b1, b2, b3, bAddr + j2 * (16 * RSTRIDE_B) + k0 * 32);
            mma_bf16(acc[j2 * 2],     a0, a1, a2, a3, b0, b1);
            mma_bf16(acc[j2 * 2 + 1], a0, a1, a2, a3, b2, b3);
        }
    }
}

// ---------------- kernel 1: zero accumulator ----------------
__global__ void k_zero(int n4) {
    int i = blockIdx.x * blockDim.x + threadIdx.x;
    int stride = gridDim.x * blockDim.x;
    float4 z = make_float4(0.f, 0.f, 0.f, 0.f);
    for (; i < n4; i += stride) g_accum4[i] = z;
    if (blockIdx.x == 0 && threadIdx.x < 16) g_hist[threadIdx.x] = 0;
}

// ---------------- kernel 2: bucket histogram ----------------
__global__ void k_hist(const float* __restrict__ dist, int E) {
    __shared__ int lh[NBUCKETS];
    if (threadIdx.x < NBUCKETS) lh[threadIdx.x] = 0;
    __syncthreads();
    int i = blockIdx.x * blockDim.x + threadIdx.x;
    int stride = gridDim.x * blockDim.x;
    for (; i < E; i += stride) atomicAdd(&lh[bucket_of(dist[i])], 1);
    __syncthreads();
    if (threadIdx.x < NBUCKETS) atomicAdd(&g_hist[threadIdx.x], lh[threadIdx.x]);
}

// ---------------- kernel 3: tiny scan ----------------
__global__ void k_scan() {
    if (threadIdx.x == 0 && blockIdx.x == 0) {
        int off = 0, toff = 0;
        for (int s = 0; s < NBUCKETS; s++) {
            int c = g_hist[s];
            g_start[s] = off; g_cursor[s] = off; g_count[s] = c; g_tileOff[s] = toff;
            off += c;
            toff += (c + TILE_M - 1) / TILE_M;
        }
        g_tileOff[NBUCKETS] = toff;
    }
}

// ---------------- kernel 4: match-aggregated scatter (counting sort) ----------------
__global__ void k_scatter(const float* __restrict__ dist, int E) {
    int lane = threadIdx.x & 31;
    unsigned ltmask = (1u << lane) - 1u;
    int i = blockIdx.x * blockDim.x + threadIdx.x;
    int stride = gridDim.x * blockDim.x;
    for (; i < E; i += stride) {
        int s = bucket_of(dist[i]);
        unsigned m = __match_any_sync(0xffffffffu, s);
        int leader = __ffs(m) - 1;
        int base = 0;
        if (lane == leader) base = atomicAdd(&g_cursor[s], __popc(m));
        base = __shfl_sync(0xffffffffu, base, leader);
        g_perm[base + __popc(m & ltmask)] = i;
    }
}

// ---------------- kernel 4b: pre-split weights (experts transposed, MLP direct) ----------------
__global__ void k_wprep(const float* __restrict__ sel_w, const float* __restrict__ w1,
                        const float* __restrict__ w2, const float* __restrict__ w3,
                        const float* __restrict__ wout) {
    int slot = blockIdx.x;
    const float* src;
    bool tr;
    if (slot < 8) { src = sel_w + (size_t)slot * (H * H); tr = true; }
    else {
        const float* m[4] = {w1, w2, w3, wout};
        src = m[slot - 8]; tr = false;
    }
    for (int idx = threadIdx.x; idx < H * H; idx += blockDim.x) {
        int n = idx >> 7, k = idx & 127;
        float w = tr ? src[k * H + n] : src[n * H + k];
        __nv_bfloat16 hh = __float2bfloat16_rn(w);
        __nv_bfloat16 ll = __float2bfloat16_rn(w - __bfloat162float(hh));
        g_wsp_hi[slot][n][k] = hh;
        g_wsp_lo[slot][n][k] = ll;
    }
}

// ---------------- kernel 5: edge expert GEMM (mma.sync bf16 split-2) + scatter ----------------
#define SM_META 0
#define SM_PERM 64
#define SM_NODE 576
#define SM_RBF  1088
#define SM_WT   4160
#define SM_AHI  7424
#define SM_ALO  (SM_AHI + 128 * RSTRIDE_B)
#define SM_BHI  (SM_ALO + 128 * RSTRIDE_B)
#define SM_BLO  (SM_BHI + 128 * RSTRIDE_B)
#define EDGE_SMEM_BYTES (SM_BLO + 128 * RSTRIDE_B)

__global__ void __launch_bounds__(THREADS, 1)
k_edge(const float* __restrict__ x, const float* __restrict__ rbf,
       const int* __restrict__ eidx, const float* __restrict__ w_rbf)
{
    extern __shared__ char sm[];
    int*   meta  = (int*)(sm + SM_META);
    int*   sPerm = (int*)(sm + SM_PERM);
    int*   sNode = (int*)(sm + SM_NODE);
    float* sRbf  = (float*)(sm + SM_RBF);
    float* sWT   = (float*)(sm + SM_WT);

    int t = threadIdx.x;
    int wid = t >> 5, lane = t & 31;

    if (t == 0) {
        int b = blockIdx.x;
        int found = -1, t0s = 0;
        #pragma unroll
        for (int q = 0; q < NBUCKETS; q++)
            if (b >= g_tileOff[q] && b < g_tileOff[q + 1]) { found = q; t0s = g_tileOff[q]; }
        if (found < 0) { meta[0] = -1; meta[1] = 0; meta[2] = 0; }
        else {
            int rowBase = (b - t0s) * TILE_M;
            meta[0] = found;
            meta[1] = min(TILE_M, g_count[found] - rowBase);
            meta[2] = g_start[found] + rowBase;
        }
    }
    __syncthreads();
    int s = meta[0], rows = meta[1], base = meta[2];
    if (s < 0) return;

    if (t < TILE_M) {
        int pe = (t < rows) ? g_perm[base + t] : 0;
        sPerm[t] = pe;
        sNode[t] = eidx[pe];
    }
    for (int idx = t; idx < 768; idx += THREADS) {           // transpose w_rbf -> [q][c]
        int q = idx >> 7, c = idx & 127;
        sWT[idx] = w_rbf[c * 6 + q];
    }
    __syncthreads();
    for (int idx = t; idx < rows * 6; idx += THREADS) {      // gather rbf rows
        int r = idx / 6;
        sRbf[idx] = rbf[(size_t)sPerm[r] * 6 + (idx - r * 6)];
    }
    if (s < 8) {                                             // copy pre-split expert weight
        const uint4* sh = (const uint4*)&g_wsp_hi[s][0][0];
        const uint4* sl = (const uint4*)&g_wsp_lo[s][0][0];
        uint4* dh = (uint4*)(sm + SM_BHI);
        uint4* dl = (uint4*)(sm + SM_BLO);
        for (int i = t; i < 128 * RSTRIDE_B / 16; i += THREADS) { dh[i] = sh[i]; dl[i] = sl[i]; }
    }
    __syncthreads();

    // ---- build h = (rbf @ w_rbf^T) * x, split bf16 hi/lo into A smem ----
    int c0 = lane * 4;
    float4 wq[6];
    #pragma unroll
    for (int q = 0; q < 6; q++) wq[q] = *(float4*)&sWT[q * 128 + c0];

    #pragma unroll 2
    for (int m = 0; m < 16; m++) {
        int r = wid * 16 + m;
        bool act = (r < rows);
        int pe = sPerm[r];
        float rq0 = sRbf[r * 6 + 0], rq1 = sRbf[r * 6 + 1], rq2 = sRbf[r * 6 + 2];
        float rq3 = sRbf[r * 6 + 3], rq4 = sRbf[r * 6 + 4], rq5 = sRbf[r * 6 + 5];
        float4 g;
        g.x = rq0*wq[0].x + rq1*wq[1].x + rq2*wq[2].x + rq3*wq[3].x + rq4*wq[4].x + rq5*wq[5].x;
        g.y = rq0*wq[0].y + rq1*wq[1].y + rq2*wq[2].y + rq3*wq[3].y + rq4*wq[4].y + rq5*wq[5].y;
        g.z = rq0*wq[0].z + rq1*wq[1].z + rq2*wq[2].z + rq3*wq[3].z + rq4*wq[4].z + rq5*wq[5].z;
        g.w = rq0*wq[0].w + rq1*wq[1].w + rq2*wq[2].w + rq3*wq[3].w + rq4*wq[4].w + rq5*wq[5].w;
        float4 xv = *(const float4*)&x[(size_t)pe * H + c0];
        float h0 = act ? g.x * xv.x : 0.f;
        float h1 = act ? g.y * xv.y : 0.f;
        float h2 = act ? g.z * xv.z : 0.f;
        float h3 = act ? g.w * xv.w : 0.f;

        if (s < 8) {
            uint32_t lo0, lo1;
            uint32_t hi0 = split2(h0, h1, lo0);
            uint32_t hi1 = split2(h2, h3, lo1);
            uint32_t off = (uint32_t)r * RSTRIDE_B + (uint32_t)c0 * 2;
            *(uint32_t*)(sm + SM_AHI + off)     = hi0;
            *(uint32_t*)(sm + SM_AHI + off + 4) = hi1;
            *(uint32_t*)(sm + SM_ALO + off)     = lo0;
            *(uint32_t*)(sm + SM_ALO + off + 4) = lo1;
        } else if (act) {
            red_add_v4((float*)g_accum4 + (size_t)sNode[r] * H + c0, h0, h1, h2, h3);
        }
    }
    if (s == 8) return;
    __syncthreads();

    // ---- mma: D = Ah*Bh + Ah*Bl + Al*Bh ----
    uint32_t sbase = smem_u32(sm);
    int m0 = wid * 16;
    float acc[16][4];
    #pragma unroll
    for (int j = 0; j < 16; j++) { acc[j][0] = acc[j][1] = acc[j][2] = acc[j][3] = 0.f; }
    mma_stripe(acc, sbase + SM_AHI, sbase + SM_BHI, lane, m0);
    mma_stripe(acc, sbase + SM_AHI, sbase + SM_BLO, lane, m0);
    mma_stripe(acc, sbase + SM_ALO, sbase + SM_BHI, lane, m0);

    // ---- scatter D to node accumulator ----
    int r0 = m0 + (lane >> 2), r1 = r0 + 8;
    int cb = (lane & 3) * 2;
    bool a0 = r0 < rows, a1 = r1 < rows;
    float* base0 = (float*)g_accum4 + (size_t)sNode[r0] * H + cb;
    float* base1 = (float*)g_accum4 + (size_t)sNode[r1] * H + cb;
    #pragma unroll
    for (int j = 0; j < 16; j++) {
        if (a0) red_add_v2(base0 + j * 8, acc[j][0], acc[j][1]);
        if (a1) red_add_v2(base1 + j * 8, acc[j][2], acc[j][3]);
    }
}

// ---------------- kernel 6: fused node MLP on mma.sync ----------------
#define MSM_BIAS 0
#define MSM_AHI  1024
#define MSM_ALO  (MSM_AHI + 128 * RSTRIDE_B)
#define MSM_WHI  (MSM_ALO + 128 * RSTRIDE_B)
#define MSM_WLO  (MSM_WHI + 128 * RSTRIDE_B)
#define MLP_SMEM_BYTES (MSM_WLO + 128 * RSTRIDE_B)

__global__ void __launch_bounds__(THREADS, 1)
k_mlp(const float* __restrict__ b1, const float* __restrict__ b2,
      const float* __restrict__ b3, float* __restrict__ out, int N)
{
    extern __shared__ char sm[];
    float* sBias = (float*)(sm + MSM_BIAS);
    int t = threadIdx.x;
    int wid = t >> 5, lane = t & 31;
    int nb = blockIdx.x * 128;
    int rows = min(128, N - nb);

    // load accumulator rows, split to bf16 hi/lo A tile
    const float* accum = (const float*)g_accum4;
    for (int idx = t; idx < 128 * 64; idx += THREADS) {
        int r = idx >> 6, cp = (idx & 63) * 2;
        float2 v = (r < rows) ? *(const float2*)&accum[(size_t)(nb + r) * H + cp]
                              : make_float2(0.f, 0.f);
        uint32_t lo;
        uint32_t hi = split2(v.x, v.y, lo);
        uint32_t off = (uint32_t)r * RSTRIDE_B + (uint32_t)cp * 2;
        *(uint32_t*)(sm + MSM_AHI + off) = hi;
        *(uint32_t*)(sm + MSM_ALO + off) = lo;
    }

    const float* Bs[3] = {b1, b2, b3};
    uint32_t sbase = smem_u32(sm);
    int m0 = wid * 16;
    int r0 = m0 + (lane >> 2), r1 = r0 + 8;
    int cb = (lane & 3) * 2;

    for (int l = 0; l < 4; l++) {
        // copy pre-split weight slot 8+l
        {
            const uint4* sh = (const uint4*)&g_wsp_hi[8 + l][0][0];
            const uint4* sl = (const uint4*)&g_wsp_lo[8 + l][0][0];
            uint4* dh = (uint4*)(sm + MSM_WHI);
            uint4* dl = (uint4*)(sm + MSM_WLO);
            for (int i = t; i < 128 * RSTRIDE_B / 16; i += THREADS) { dh[i] = sh[i]; dl[i] = sl[i]; }
            if (l < 3 && t < 128) sBias[t] = Bs[l][t];
        }
        __syncthreads();

        float acc[16][4];
        #pragma unroll
        for (int j = 0; j < 16; j++) { acc[j][0] = acc[j][1] = acc[j][2] = acc[j][3] = 0.f; }
        mma_stripe(acc, sbase + MSM_AHI, sbase + MSM_WHI, lane, m0);
        mma_stripe(acc, sbase + MSM_AHI, sbase + MSM_WLO, lane, m0);
        mma_stripe(acc, sbase + MSM_ALO, sbase + MSM_WHI, lane, m0);
        __syncthreads();   // all reads of A done before epilogue overwrites

        if (l < 3) {
            #pragma unroll
            for (int j = 0; j < 16; j++) {
                int col = j * 8 + cb;
                float v0 = acc[j][0] + sBias[col];
                float v1 = acc[j][1] + sBias[col + 1];
                float v2 = acc[j][2] + sBias[col];
                float v3 = acc[j][3] + sBias[col + 1];
                v0 = v0 / (1.f + __expf(-v0));
                v1 = v1 / (1.f + __expf(-v1));
                v2 = v2 / (1.f + __expf(-v2));
                v3 = v3 / (1.f + __expf(-v3));
                uint32_t lo0, lo1;
                uint32_t hi0 = split2(v0, v1, lo0);
                uint32_t hi1 = split2(v2, v3, lo1);
                uint32_t off0 = (uint32_t)r0 * RSTRIDE_B + (uint32_t)col * 2;
                uint32_t off1 = (uint32_t)r1 * RSTRIDE_B + (uint32_t)col * 2;
                *(uint32_t*)(sm + MSM_AHI + off0) = hi0;
                *(uint32_t*)(sm + MSM_ALO + off0) = lo0;
                *(uint32_t*)(sm + MSM_AHI + off1) = hi1;
                *(uint32_t*)(sm + MSM_ALO + off1) = lo1;
            }
        } else {
            #pragma unroll
            for (int j = 0; j < 16; j++) {
                int col = j * 8 + cb;
                if (r0 < rows)
                    *(float2*)&out[(size_t)(nb + r0) * H + col] = make_float2(acc[j][0], acc[j][1]);
                if (r1 < rows)
                    *(float2*)&out[(size_t)(nb + r1) * H + col] = make_float2(acc[j][2], acc[j][3]);
            }
        }
    }
}

// ---------------- launcher ----------------
extern "C" void kernel_launch(void* const* d_in, const int* in_sizes, int n_in,
                              void* d_out, int out_size)
{
    const float* x    = (const float*)d_in[0];
    const float* rbf  = (const float*)d_in[1];
    const int*   ei   = (const int*)  d_in[2];
    const float* dist = (const float*)d_in[3];
    int k = 4;
    while (k < n_in && in_sizes[k] != 768) k++;
    const float* w_rbf = (const float*)d_in[k];
    const float* sel_w = (const float*)d_in[k + 1];
    const float* w1    = (const float*)d_in[k + 2];
    const float* b1    = (const float*)d_in[k + 3];
    const float* w2    = (const float*)d_in[k + 4];
    const float* b2    = (const float*)d_in[k + 5];
    const float* w3    = (const float*)d_in[k + 6];
    const float* b3    = (const float*)d_in[k + 7];
    const float* wout  = (const float*)d_in[k + 8];

    int E = in_sizes[0] / H;
    int N = out_size / H;

    cudaFuncSetAttribute(k_edge, cudaFuncAttributeMaxDynamicSharedMemorySize, EDGE_SMEM_BYTES);
    cudaFuncSetAttribute(k_mlp,  cudaFuncAttributeMaxDynamicSharedMemorySize, MLP_SMEM_BYTES);

    k_zero<<<512, 256>>>(N * (H / 4));
    k_hist<<<1024, 256>>>(dist, E);
    k_scan<<<1, 1>>>();
    k_scatter<<<1024, 256>>>(dist, E);
    k_wprep<<<12, 256>>>(sel_w, w1, w2, w3, wout);

    int tiles = (E + TILE_M - 1) / TILE_M + NBUCKETS;
    k_edge<<<tiles, THREADS, EDGE_SMEM_BYTES>>>(x, rbf, ei, w_rbf);
    k_mlp<<<(N + 127) / 128, THREADS, MLP_SMEM_BYTES>>>(b1, b2, b3, (float*)d_out, N);
}

// round 4
// speedup vs baseline: 2.2147x; 1.5371x over previous
#include <cuda_runtime.h>
#include <cuda_bf16.h>
#include <cstdint>

#define H 128
#define NBUCKETS 9     // 8 expert buckets + 1 passthrough
#define THREADS 256
#define G_TILES 8      // tiles per CTA group (same bucket -> B amortized)

// row stride for bf16 operand tiles: 136 elems = 272B = 17*16B (odd -> ldmatrix conflict-free)
#define RSTRIDE_E 136
#define RSTRIDE_B 272
#define SD_STRIDE 132  // f32 staging stride (132 ~= 4 mod 32 banks)

// ---------------- device scratch ----------------
__device__ float4 g_accum4[100000 * (H / 4)];
__device__ int    g_perm[1000000];
__device__ int    g_hist[16];
__device__ int    g_start[NBUCKETS];
__device__ int    g_count[NBUCKETS];
__device__ int    g_cursor[NBUCKETS];
__device__ int    g_groupOff[NBUCKETS + 1];
// pre-split weights: slot 0..7 experts (B^T[n][k]=W[k][n]), slot 8..11 = w1,w2,w3,wout
__device__ __align__(16) __nv_bfloat16 g_wsp_hi[12][128][RSTRIDE_E];
__device__ __align__(16) __nv_bfloat16 g_wsp_lo[12][128][RSTRIDE_E];

// ---------------- helpers ----------------
__device__ __forceinline__ int bucket_of(float d) {
    float t = (d - 0.8f) / 5.0001f * 8.0f;
    float f = floorf(t);
    return (f >= 0.0f && f < 8.0f) ? (int)f : 8;
}

__device__ __forceinline__ void red_add_v4(float* p, float a, float b, float c, float d) {
    asm volatile("red.global.add.v4.f32 [%0], {%1,%2,%3,%4};"
                 :: "l"(p), "f"(a), "f"(b), "f"(c), "f"(d) : "memory");
}

__device__ __forceinline__ uint32_t smem_u32(const void* p) {
    uint32_t a;
    asm("{ .reg .u64 t; cvta.to.shared.u64 t, %1; cvt.u32.u64 %0, t; }" : "=r"(a) : "l"(p));
    return a;
}

#define CP16(dst, src) asm volatile("cp.async.cg.shared.global [%0], [%1], 16;" :: "r"(dst), "l"(src))
#define CP8(dst, src)  asm volatile("cp.async.ca.shared.global [%0], [%1], 8;"  :: "r"(dst), "l"(src))
#define CP_COMMIT()    asm volatile("cp.async.commit_group;" ::: "memory")
#define CP_WAIT0()     asm volatile("cp.async.wait_group 0;" ::: "memory")

__device__ __forceinline__ void ldsm_x4(uint32_t& r0, uint32_t& r1, uint32_t& r2, uint32_t& r3,
                                        uint32_t addr) {
    asm volatile("ldmatrix.sync.aligned.m8n8.x4.shared.b16 {%0,%1,%2,%3}, [%4];"
                 : "=r"(r0), "=r"(r1), "=r"(r2), "=r"(r3) : "r"(addr));
}

__device__ __forceinline__ void mma_bf16(float* d, uint32_t a0, uint32_t a1, uint32_t a2,
                                         uint32_t a3, uint32_t b0, uint32_t b1) {
    asm volatile("mma.sync.aligned.m16n8k16.row.col.f32.bf16.bf16.f32 "
                 "{%0,%1,%2,%3}, {%4,%5,%6,%7}, {%8,%9}, {%0,%1,%2,%3};"
                 : "+f"(d[0]), "+f"(d[1]), "+f"(d[2]), "+f"(d[3])
                 : "r"(a0), "r"(a1), "r"(a2), "r"(a3), "r"(b0), "r"(b1));
}

__device__ __forceinline__ uint32_t split2(float v0, float v1, uint32_t& lo) {
    __nv_bfloat16 h0 = __float2bfloat16_rn(v0), h1 = __float2bfloat16_rn(v1);
    __nv_bfloat16 l0 = __float2bfloat16_rn(v0 - __bfloat162float(h0));
    __nv_bfloat16 l1 = __float2bfloat16_rn(v1 - __bfloat162float(h1));
    lo = (uint32_t)__bfloat16_as_ushort(l0) | ((uint32_t)__bfloat16_as_ushort(l1) << 16);
    return (uint32_t)__bfloat16_as_ushort(h0) | ((uint32_t)__bfloat16_as_ushort(h1) << 16);
}

// acc[16][4] += A(16x128 stripe at m0, bf16 s272) * B^T(128x128 bf16 s272)
__device__ __forceinline__ void mma_stripe(float (*acc)[4], uint32_t aBase, uint32_t bBase,
                                           int lane, int m0) {
    uint32_t aAddr = aBase + (uint32_t)(m0 + (lane & 15)) * RSTRIDE_B
                   + (uint32_t)((lane >> 4) << 4);
    uint32_t bAddr = bBase + (uint32_t)((lane & 7) + ((lane >> 4) << 3)) * RSTRIDE_B
                   + (uint32_t)(((lane >> 3) & 1) << 4);
    #pragma unroll
    for (int k0 = 0; k0 < 8; k0++) {
        uint32_t a0, a1, a2, a3;
        ldsm_x4(a0, a1, a2, a3, aAddr + k0 * 32);
        #pragma unroll
        for (int j2 = 0; j2 < 8; j2++) {
            uint32_t b0, b1, b2, b3;
            ldsm_x4(b0, b1, b2, b3, bAddr + j2 * (16 * RSTRIDE_B) + k0 * 32);
            mma_bf16(acc[j2 * 2],     a0, a1, a2, a3, b0, b1);
            mma_bf16(acc[j2 * 2 + 1], a0, a1, a2, a3, b2, b3);
        }
    }
}

// ---------------- small kernels ----------------
__global__ void k_zero(int n4) {
    int i = blockIdx.x * blockDim.x + threadIdx.x;
    int stride = gridDim.x * blockDim.x;
    float4 z = make_float4(0.f, 0.f, 0.f, 0.f);
    for (; i < n4; i += stride) g_accum4[i] = z;
    if (blockIdx.x == 0 && threadIdx.x < 16) g_hist[threadIdx.x] = 0;
}

__global__ void k_hist(const float* __restrict__ dist, int E) {
    __shared__ int lh[NBUCKETS];
    if (threadIdx.x < NBUCKETS) lh[threadIdx.x] = 0;
    __syncthreads();
    int i = blockIdx.x * blockDim.x + threadIdx.x;
    int stride = gridDim.x * blockDim.x;
    for (; i < E; i += stride) atomicAdd(&lh[bucket_of(dist[i])], 1);
    __syncthreads();
    if (threadIdx.x < NBUCKETS) atomicAdd(&g_hist[threadIdx.x], lh[threadIdx.x]);
}

__global__ void k_scan() {
    if (threadIdx.x == 0 && blockIdx.x == 0) {
        int off = 0, goff = 0;
        for (int s = 0; s < NBUCKETS; s++) {
            int c = g_hist[s];
            g_start[s] = off; g_cursor[s] = off; g_count[s] = c;
            g_groupOff[s] = goff;
            off += c;
            goff += (c + G_TILES * 128 - 1) / (G_TILES * 128);
        }
        g_groupOff[NBUCKETS] = goff;
    }
}

__global__ void k_scatter(const float* __restrict__ dist, int E) {
    int lane = threadIdx.x & 31;
    unsigned ltmask = (1u << lane) - 1u;
    int i = blockIdx.x * blockDim.x + threadIdx.x;
    int stride = gridDim.x * blockDim.x;
    for (; i < E; i += stride) {
        int s = bucket_of(dist[i]);
        unsigned m = __match_any_sync(0xffffffffu, s);
        int leader = __ffs(m) - 1;
        int base = 0;
        if (lane == leader) base = atomicAdd(&g_cursor[s], __popc(m));
        base = __shfl_sync(0xffffffffu, base, leader);
        g_perm[base + __popc(m & ltmask)] = i;
    }
}

__global__ void k_wprep(const float* __restrict__ sel_w, const float* __restrict__ w1,
                        const float* __restrict__ w2, const float* __restrict__ w3,
                        const float* __restrict__ wout) {
    int slot = blockIdx.x;
    const float* src;
    bool tr;
    if (slot < 8) { src = sel_w + (size_t)slot * (H * H); tr = true; }
    else {
        const float* m[4] = {w1, w2, w3, wout};
        src = m[slot - 8]; tr = false;
    }
    for (int idx = threadIdx.x; idx < H * H; idx += blockDim.x) {
        int n = idx >> 7, k = idx & 127;
        float w = tr ? src[k * H + n] : src[n * H + k];
        __nv_bfloat16 hh = __float2bfloat16_rn(w);
        __nv_bfloat16 ll = __float2bfloat16_rn(w - __bfloat162float(hh));
        g_wsp_hi[slot][n][k] = hh;
        g_wsp_lo[slot][n][k] = ll;
    }
}

// ---------------- kernel 5: grouped, pipelined edge expert GEMM ----------------
// smem byte layout
#define SM_META 0
#define SM_WT   32                         // 768 floats
#define SM_PERM (SM_WT + 3072)             // G*128 ints
#define SM_NODE (SM_PERM + 4096)
#define SM_RBF  (SM_NODE + 4096)           // 128*6 floats (per-tile staging)
#define SM_XBUF (SM_RBF + 3072 + 32)       // 128 rows x 512B
#define SM_AHI  (SM_XBUF + 65536)
#define SM_ALO  (SM_AHI + 34816)
#define SM_BHI  (SM_ALO + 34816)
#define SM_BLO  (SM_BHI + 34816)
#define EDGE_SMEM_BYTES (SM_BLO + 34816)

__device__ __forceinline__ void issue_tile(const float* x, const float* rbf,
                                           const int* pt, uint32_t sbase, int t) {
    #pragma unroll 4
    for (int idx = t; idx < 4096; idx += THREADS) {
        int r = idx >> 5, seg = idx & 31;
        const char* src = (const char*)(x + (size_t)pt[r] * H) + seg * 16;
        CP16(sbase + SM_XBUF + r * 512 + seg * 16, src);
    }
    for (int idx = t; idx < 384; idx += THREADS) {
        int r = idx / 3, p = idx - r * 3;
        const char* src = (const char*)(rbf + (size_t)pt[r] * 6) + p * 8;
        CP8(sbase + SM_RBF + r * 24 + p * 8, src);
    }
}

__global__ void __launch_bounds__(THREADS, 1)
k_edge(const float* __restrict__ x, const float* __restrict__ rbf,
       const int* __restrict__ eidx, const float* __restrict__ w_rbf)
{
    extern __shared__ char sm[];
    int*   meta  = (int*)(sm + SM_META);
    float* sWT   = (float*)(sm + SM_WT);
    int*   permG = (int*)(sm + SM_PERM);
    int*   nodeG = (int*)(sm + SM_NODE);
    float* sRbf  = (float*)(sm + SM_RBF);
    uint32_t sbase = smem_u32(sm);

    int t = threadIdx.x, wid = t >> 5, lane = t & 31;

    if (t == 0) {
        int b = blockIdx.x;
        int found = -1, grpLocal = 0;
        if (b < g_groupOff[NBUCKETS]) {
            #pragma unroll
            for (int q = 0; q < NBUCKETS; q++)
                if (b >= g_groupOff[q] && b < g_groupOff[q + 1]) { found = q; grpLocal = b - g_groupOff[q]; }
        }
        if (found < 0) meta[0] = -1;
        else {
            int rowBase = grpLocal * (G_TILES * 128);
            int rem = g_count[found] - rowBase;
            if (rem > G_TILES * 128) rem = G_TILES * 128;
            meta[0] = found;
            meta[1] = (rem + 127) >> 7;
            meta[2] = g_start[found] + rowBase;
            meta[3] = rem;
        }
    }
    __syncthreads();
    int s = meta[0];
    if (s < 0) return;
    int nTiles = meta[1], rowStart = meta[2], rem = meta[3];

    for (int idx = t; idx < nTiles * 128; idx += THREADS)
        permG[idx] = (idx < rem) ? g_perm[rowStart + idx] : g_perm[rowStart];
    for (int idx = t; idx < 768; idx += THREADS) {
        int q = idx >> 7, c = idx & 127;
        sWT[idx] = w_rbf[c * 6 + q];
    }
    __syncthreads();
    for (int idx = t; idx < nTiles * 128; idx += THREADS)
        nodeG[idx] = eidx[permG[idx]];

    // async: expert weight (once per group) + first tile's x/rbf
    if (s < 8) {
        const char* srcH = (const char*)&g_wsp_hi[s][0][0];
        const char* srcL = (const char*)&g_wsp_lo[s][0][0];
        for (int i = t * 16; i < 34816; i += THREADS * 16) {
            CP16(sbase + SM_BHI + i, srcH + i);
            CP16(sbase + SM_BLO + i, srcL + i);
        }
    }
    issue_tile(x, rbf, permG, sbase, t);
    CP_COMMIT();
    CP_WAIT0();
    __syncthreads();

    int c0 = lane * 4;
    float4 wq[6];
    #pragma unroll
    for (int q = 0; q < 6; q++) wq[q] = *(float4*)&sWT[q * 128 + c0];
    int m0 = wid * 16;
    int r0s = m0 + (lane >> 2), r1s = r0s + 8, cbs = (lane & 3) * 2;

    for (int i = 0; i < nTiles; i++) {
        int rows_i = min(128, rem - i * 128);
        const int* nodeT = nodeG + i * 128;

        // ---- build A(i) from staged x/rbf ----
        #pragma unroll 2
        for (int m = 0; m < 16; m++) {
            int r = m0 + m;
            bool act = (r < rows_i);
            const float* xr = (const float*)(sm + SM_XBUF + r * 512);
            float rq0 = sRbf[r * 6 + 0], rq1 = sRbf[r * 6 + 1], rq2 = sRbf[r * 6 + 2];
            float rq3 = sRbf[r * 6 + 3], rq4 = sRbf[r * 6 + 4], rq5 = sRbf[r * 6 + 5];
            float4 g;
            g.x = rq0*wq[0].x + rq1*wq[1].x + rq2*wq[2].x + rq3*wq[3].x + rq4*wq[4].x + rq5*wq[5].x;
            g.y = rq0*wq[0].y + rq1*wq[1].y + rq2*wq[2].y + rq3*wq[3].y + rq4*wq[4].y + rq5*wq[5].y;
            g.z = rq0*wq[0].z + rq1*wq[1].z + rq2*wq[2].z + rq3*wq[3].z + rq4*wq[4].z + rq5*wq[5].z;
            g.w = rq0*wq[0].w + rq1*wq[1].w + rq2*wq[2].w + rq3*wq[3].w + rq4*wq[4].w + rq5*wq[5].w;
            float4 xv = *(const float4*)&xr[c0];
            float h0 = act ? g.x * xv.x : 0.f;
            float h1 = act ? g.y * xv.y : 0.f;
            float h2 = act ? g.z * xv.z : 0.f;
            float h3 = act ? g.w * xv.w : 0.f;
            if (s < 8) {
                uint32_t lo0, lo1;
                uint32_t hi0 = split2(h0, h1, lo0);
                uint32_t hi1 = split2(h2, h3, lo1);
                uint32_t off = (uint32_t)r * RSTRIDE_B + (uint32_t)c0 * 2;
                *(uint32_t*)(sm + SM_AHI + off)     = hi0;
                *(uint32_t*)(sm + SM_AHI + off + 4) = hi1;
                *(uint32_t*)(sm + SM_ALO + off)     = lo0;
                *(uint32_t*)(sm + SM_ALO + off + 4) = lo1;
            } else if (act) {
                red_add_v4((float*)g_accum4 + (size_t)nodeT[r] * H + c0, h0, h1, h2, h3);
            }
        }
        __syncthreads();

        // ---- prefetch next tile while MMA runs ----
        if (i + 1 < nTiles) issue_tile(x, rbf, permG + (i + 1) * 128, sbase, t);
        CP_COMMIT();

        if (s < 8) {
            float acc[16][4];
            #pragma unroll
            for (int j = 0; j < 16; j++) { acc[j][0] = acc[j][1] = acc[j][2] = acc[j][3] = 0.f; }
            mma_stripe(acc, sbase + SM_AHI, sbase + SM_BHI, lane, m0);
            mma_stripe(acc, sbase + SM_AHI, sbase + SM_BLO, lane, m0);
            mma_stripe(acc, sbase + SM_ALO, sbase + SM_BHI, lane, m0);
            __syncthreads();                       // all A reads done

            // ---- stage D into (now free) A region, then red.v4 scatter ----
            float* sD = (float*)(sm + SM_AHI);
            #pragma unroll
            for (int j = 0; j < 16; j++) {
                int col = j * 8 + cbs;
                *(float2*)&sD[r0s * SD_STRIDE + col] = make_float2(acc[j][0], acc[j][1]);
                *(float2*)&sD[r1s * SD_STRIDE + col] = make_float2(acc[j][2], acc[j][3]);
            }
            __syncthreads();
            #pragma unroll 4
            for (int idx = t; idx < 4096; idx += THREADS) {
                int row = idx >> 5, c4 = (idx & 31) << 2;
                if (row < rows_i) {
                    float4 v = *(float4*)&sD[row * SD_STRIDE + c4];
                    red_add_v4((float*)g_accum4 + (size_t)nodeT[row] * H + c4, v.x, v.y, v.z, v.w);
                }
            }
        }
        CP_WAIT0();
        __syncthreads();
    }
}

// ---------------- kernel 6: fused node MLP, weights double-buffered ----------------
#define MSM_BIAS 0                          // 3*128 floats
#define MSM_AHI  1536
#define MSM_ALO  (MSM_AHI + 34816)
#define MSM_W    (MSM_ALO + 34816)          // 2 bufs x (hi 34816 + lo 34816)
#define MLP_SMEM_BYTES (MSM_W + 2 * 69632)

__device__ __forceinline__ void issue_weight(int slot, int buf, uint32_t sbase, int t) {
    const char* srcH = (const char*)&g_wsp_hi[slot][0][0];
    const char* srcL = (const char*)&g_wsp_lo[slot][0][0];
    uint32_t dst = sbase + MSM_W + (uint32_t)buf * 69632;
    for (int i = t * 16; i < 34816; i += THREADS * 16) {
        CP16(dst + i, srcH + i);
        CP16(dst + 34816 + i, srcL + i);
    }
}

__global__ void __launch_bounds__(THREADS, 1)
k_mlp(const float* __restrict__ b1, const float* __restrict__ b2,
      const float* __restrict__ b3, float* __restrict__ out, int N)
{
    extern __shared__ char sm[];
    float* sBias = (float*)(sm + MSM_BIAS);
    uint32_t sbase = smem_u32(sm);
    int t = threadIdx.x, wid = t >> 5, lane = t & 31;
    int nb = blockIdx.x * 128;
    int rows = min(128, N - nb);

    issue_weight(8, 0, sbase, t);
    CP_COMMIT();

    // A from accumulator, split hi/lo
    const float* accum = (const float*)g_accum4;
    for (int idx = t; idx < 128 * 32; idx += THREADS) {
        int r = idx >> 5, c4 = (idx & 31) * 4;
        float4 v = (r < rows) ? *(const float4*)&accum[(size_t)(nb + r) * H + c4]
                              : make_float4(0.f, 0.f, 0.f, 0.f);
        uint32_t lo0, lo1;
        uint32_t hi0 = split2(v.x, v.y, lo0);
        uint32_t hi1 = split2(v.z, v.w, lo1);
        uint32_t off = (uint32_t)r * RSTRIDE_B + (uint32_t)c4 * 2;
        *(uint32_t*)(sm + MSM_AHI + off)     = hi0;
        *(uint32_t*)(sm + MSM_AHI + off + 4) = hi1;
        *(uint32_t*)(sm + MSM_ALO + off)     = lo0;
        *(uint32_t*)(sm + MSM_ALO + off + 4) = lo1;
    }
    if (t < 128) {
        sBias[t]       = b1[t];
        sBias[t + 128] = b2[t];
        sBias[t + 256] = b3[t];
    }

    int m0 = wid * 16;
    int r0 = m0 + (lane >> 2), r1 = r0 + 8, cb = (lane & 3) * 2;

    for (int l = 0; l < 4; l++) {
        CP_WAIT0();
        __syncthreads();
        if (l < 3) { issue_weight(9 + l, (l + 1) & 1, sbase, t); CP_COMMIT(); }

        uint32_t wb = sbase + MSM_W + (uint32_t)(l & 1) * 69632;
        float acc[16][4];
        #pragma unroll
        for (int j = 0; j < 16; j++) { acc[j][0] = acc[j][1] = acc[j][2] = acc[j][3] = 0.f; }
        mma_stripe(acc, sbase + MSM_AHI, wb,         lane, m0);
        mma_stripe(acc, sbase + MSM_AHI, wb + 34816, lane, m0);
        mma_stripe(acc, sbase + MSM_ALO, wb,         lane, m0);
        __syncthreads();   // A reads done before epilogue overwrite

        if (l < 3) {
            const float* bias = sBias + l * 128;
            #pragma unroll
            for (int j = 0; j < 16; j++) {
                int col = j * 8 + cb;
                float v0 = acc[j][0] + bias[col];
                float v1 = acc[j][1] + bias[col + 1];
                float v2 = acc[j][2] + bias[col];
                float v3 = acc[j][3] + bias[col + 1];
                v0 = v0 / (1.f + __expf(-v0));
                v1 = v1 / (1.f + __expf(-v1));
                v2 = v2 / (1.f + __expf(-v2));
                v3 = v3 / (1.f + __expf(-v3));
                uint32_t lo0, lo1;
                uint32_t hi0 = split2(v0, v1, lo0);
                uint32_t hi1 = split2(v2, v3, lo1);
                uint32_t off0 = (uint32_t)r0 * RSTRIDE_B + (uint32_t)col * 2;
                uint32_t off1 = (uint32_t)r1 * RSTRIDE_B + (uint32_t)col * 2;
                *(uint32_t*)(sm + MSM_AHI + off0) = hi0;
                *(uint32_t*)(sm + MSM_ALO + off0) = lo0;
                *(uint32_t*)(sm + MSM_AHI + off1) = hi1;
                *(uint32_t*)(sm + MSM_ALO + off1) = lo1;
            }
        } else {
            #pragma unroll
            for (int j = 0; j < 16; j++) {
                int col = j * 8 + cb;
                if (r0 < rows)
                    *(float2*)&out[(size_t)(nb + r0) * H + col] = make_float2(acc[j][0], acc[j][1]);
                if (r1 < rows)
                    *(float2*)&out[(size_t)(nb + r1) * H + col] = make_float2(acc[j][2], acc[j][3]);
            }
        }
    }
}

// ---------------- launcher ----------------
extern "C" void kernel_launch(void* const* d_in, const int* in_sizes, int n_in,
                              void* d_out, int out_size)
{
    const float* x    = (const float*)d_in[0];
    const float* rbf  = (const float*)d_in[1];
    const int*   ei   = (const int*)  d_in[2];
    const float* dist = (const float*)d_in[3];
    int k = 4;
    while (k < n_in && in_sizes[k] != 768) k++;
    const float* w_rbf = (const float*)d_in[k];
    const float* sel_w = (const float*)d_in[k + 1];
    const float* w1    = (const float*)d_in[k + 2];
    const float* b1    = (const float*)d_in[k + 3];
    const float* w2    = (const float*)d_in[k + 4];
    const float* b2    = (const float*)d_in[k + 5];
    const float* w3    = (const float*)d_in[k + 6];
    const float* b3    = (const float*)d_in[k + 7];
    const float* wout  = (const float*)d_in[k + 8];

    int E = in_sizes[0] / H;
    int N = out_size / H;

    cudaFuncSetAttribute(k_edge, cudaFuncAttributeMaxDynamicSharedMemorySize, EDGE_SMEM_BYTES);
    cudaFuncSetAttribute(k_mlp,  cudaFuncAttributeMaxDynamicSharedMemorySize, MLP_SMEM_BYTES);

    k_zero<<<512, 256>>>(N * (H / 4));
    k_hist<<<1024, 256>>>(dist, E);
    k_scan<<<1, 1>>>();
    k_scatter<<<1024, 256>>>(dist, E);
    k_wprep<<<12, 256>>>(sel_w, w1, w2, w3, wout);

    int maxGroups = (E + G_TILES * 128 - 1) / (G_TILES * 128) + NBUCKETS;
    k_edge<<<maxGroups, THREADS, EDGE_SMEM_BYTES>>>(x, rbf, ei, w_rbf);
    k_mlp<<<(N + 127) / 128, THREADS, MLP_SMEM_BYTES>>>(b1, b2, b3, (float*)d_out, N);
}

// round 5
// speedup vs baseline: 2.8848x; 1.3026x over previous
#include <cuda_runtime.h>
#include <cuda_bf16.h>
#include <cuda_fp16.h>
#include <cstdint>

#define H 128
#define NBUCKETS 9     // 8 expert buckets + 1 passthrough
#define THREADS 256
#define G_TILES 8      // tiles per CTA group (same bucket -> B amortized)

// row stride for 16-bit operand tiles: 136 elems = 272B = 17*16B (ldmatrix conflict-free)
#define RSTRIDE_E 136
#define RSTRIDE_B 272
#define SD_STRIDE 132  // f32 staging stride

// ---------------- device scratch ----------------
__device__ float4 g_accum4[100000 * (H / 4)];
__device__ int    g_perm[1000000];
__device__ int    g_hist[16];
__device__ int    g_start[NBUCKETS];
__device__ int    g_count[NBUCKETS];
__device__ int    g_cursor[NBUCKETS];
__device__ int    g_groupOff[NBUCKETS + 1];
// pre-split weights: slots 0..7 experts (fp16 pairs, B^T[n][k]=W[k][n]),
// slots 8..11 = MLP w1,w2,w3,wout (bf16 pairs, [n][k])
__device__ __align__(16) unsigned short g_wsp_hi[12][128][RSTRIDE_E];
__device__ __align__(16) unsigned short g_wsp_lo[12][128][RSTRIDE_E];

// ---------------- helpers ----------------
__device__ __forceinline__ int bucket_of(float d) {
    float t = (d - 0.8f) / 5.0001f * 8.0f;
    float f = floorf(t);
    return (f >= 0.0f && f < 8.0f) ? (int)f : 8;
}

__device__ __forceinline__ void red_add_v4(float* p, float a, float b, float c, float d) {
    asm volatile("red.global.add.v4.f32 [%0], {%1,%2,%3,%4};"
                 :: "l"(p), "f"(a), "f"(b), "f"(c), "f"(d) : "memory");
}

__device__ __forceinline__ uint32_t smem_u32(const void* p) {
    uint32_t a;
    asm("{ .reg .u64 t; cvta.to.shared.u64 t, %1; cvt.u32.u64 %0, t; }" : "=r"(a) : "l"(p));
    return a;
}

#define CP16(dst, src) asm volatile("cp.async.cg.shared.global [%0], [%1], 16;" :: "r"(dst), "l"(src))
#define CP8(dst, src)  asm volatile("cp.async.ca.shared.global [%0], [%1], 8;"  :: "r"(dst), "l"(src))
#define CP_COMMIT()    asm volatile("cp.async.commit_group;" ::: "memory")
#define CP_WAIT0()     asm volatile("cp.async.wait_group 0;" ::: "memory")

__device__ __forceinline__ void ldsm_x4(uint32_t& r0, uint32_t& r1, uint32_t& r2, uint32_t& r3,
                                        uint32_t addr) {
    asm volatile("ldmatrix.sync.aligned.m8n8.x4.shared.b16 {%0,%1,%2,%3}, [%4];"
                 : "=r"(r0), "=r"(r1), "=r"(r2), "=r"(r3) : "r"(addr));
}

__device__ __forceinline__ void mma_bf16(float* d, uint32_t a0, uint32_t a1, uint32_t a2,
                                         uint32_t a3, uint32_t b0, uint32_t b1) {
    asm volatile("mma.sync.aligned.m16n8k16.row.col.f32.bf16.bf16.f32 "
                 "{%0,%1,%2,%3}, {%4,%5,%6,%7}, {%8,%9}, {%0,%1,%2,%3};"
                 : "+f"(d[0]), "+f"(d[1]), "+f"(d[2]), "+f"(d[3])
                 : "r"(a0), "r"(a1), "r"(a2), "r"(a3), "r"(b0), "r"(b1));
}

__device__ __forceinline__ void mma_fp16(float* d, uint32_t a0, uint32_t a1, uint32_t a2,
                                         uint32_t a3, uint32_t b0, uint32_t b1) {
    asm volatile("mma.sync.aligned.m16n8k16.row.col.f32.f16.f16.f32 "
                 "{%0,%1,%2,%3}, {%4,%5,%6,%7}, {%8,%9}, {%0,%1,%2,%3};"
                 : "+f"(d[0]), "+f"(d[1]), "+f"(d[2]), "+f"(d[3])
                 : "r"(a0), "r"(a1), "r"(a2), "r"(a3), "r"(b0), "r"(b1));
}

__device__ __forceinline__ uint32_t split2_bf16(float v0, float v1, uint32_t& lo) {
    __nv_bfloat16 h0 = __float2bfloat16_rn(v0), h1 = __float2bfloat16_rn(v1);
    __nv_bfloat16 l0 = __float2bfloat16_rn(v0 - __bfloat162float(h0));
    __nv_bfloat16 l1 = __float2bfloat16_rn(v1 - __bfloat162float(h1));
    lo = (uint32_t)__bfloat16_as_ushort(l0) | ((uint32_t)__bfloat16_as_ushort(l1) << 16);
    return (uint32_t)__bfloat16_as_ushort(h0) | ((uint32_t)__bfloat16_as_ushort(h1) << 16);
}

__device__ __forceinline__ uint32_t pack_half2(float v0, float v1) {
    __half h0 = __float2half_rn(v0), h1 = __float2half_rn(v1);
    return (uint32_t)__half_as_ushort(h0) | ((uint32_t)__half_as_ushort(h1) << 16);
}

// bf16 split pass for k_mlp: acc[16][4] += A(16x128 stripe at m0) * B^T(128x128)
__device__ __forceinline__ void mma_stripe(float (*acc)[4], uint32_t aBase, uint32_t bBase,
                                           int lane, int m0) {
    uint32_t aAddr = aBase + (uint32_t)(m0 + (lane & 15)) * RSTRIDE_B
                   + (uint32_t)((lane >> 4) << 4);
    uint32_t bAddr = bBase + (uint32_t)((lane & 7) + ((lane >> 4) << 3)) * RSTRIDE_B
                   + (uint32_t)(((lane >> 3) & 1) << 4);
    #pragma unroll
    for (int k0 = 0; k0 < 8; k0++) {
        uint32_t a0, a1, a2, a3;
        ldsm_x4(a0, a1, a2, a3, aAddr + k0 * 32);
        #pragma unroll
        for (int j2 = 0; j2 < 8; j2++) {
            uint32_t b0, b1, b2, b3;
            ldsm_x4(b0, b1, b2, b3, bAddr + j2 * (16 * RSTRIDE_B) + k0 * 32);
            mma_bf16(acc[j2 * 2],     a0, a1, a2, a3, b0, b1);
            mma_bf16(acc[j2 * 2 + 1], a0, a1, a2, a3, b2, b3);
        }
    }
}

// fp16 pass for k_edge: acc[2][8][4] += A(32x128 at m0) * B^T(64 cols at n0)
__device__ __forceinline__ void mma_pass16(float (*acc)[8][4], uint32_t aBase, uint32_t bBase,
                                           int lane, int m0, int n0) {
    uint32_t aAddr = aBase + (uint32_t)(m0 + (lane & 15)) * RSTRIDE_B
                   + (uint32_t)((lane >> 4) << 4);
    uint32_t bAddr = bBase + (uint32_t)(n0 + (lane & 7) + ((lane >> 4) << 3)) * RSTRIDE_B
                   + (uint32_t)(((lane >> 3) & 1) << 4);
    #pragma unroll
    for (int k0 = 0; k0 < 8; k0++) {
        uint32_t a0, a1, a2, a3, c0, c1, c2, c3;
        ldsm_x4(a0, a1, a2, a3, aAddr + k0 * 32);
        ldsm_x4(c0, c1, c2, c3, aAddr + 16 * RSTRIDE_B + k0 * 32);
        #pragma unroll
        for (int j2 = 0; j2 < 4; j2++) {
            uint32_t b0, b1, b2, b3;
            ldsm_x4(b0, b1, b2, b3, bAddr + j2 * (16 * RSTRIDE_B) + k0 * 32);
            mma_fp16(acc[0][j2 * 2],     a0, a1, a2, a3, b0, b1);
            mma_fp16(acc[0][j2 * 2 + 1], a0, a1, a2, a3, b2, b3);
            mma_fp16(acc[1][j2 * 2],     c0, c1, c2, c3, b0, b1);
            mma_fp16(acc[1][j2 * 2 + 1], c0, c1, c2, c3, b2, b3);
        }
    }
}

// ---------------- small kernels ----------------
__global__ void k_zero(int n4) {
    int i = blockIdx.x * blockDim.x + threadIdx.x;
    int stride = gridDim.x * blockDim.x;
    float4 z = make_float4(0.f, 0.f, 0.f, 0.f);
    for (; i < n4; i += stride) g_accum4[i] = z;
    if (blockIdx.x == 0 && threadIdx.x < 16) g_hist[threadIdx.x] = 0;
}

__global__ void k_hist(const float* __restrict__ dist, int E) {
    __shared__ int lh[NBUCKETS];
    if (threadIdx.x < NBUCKETS) lh[threadIdx.x] = 0;
    __syncthreads();
    int i = blockIdx.x * blockDim.x + threadIdx.x;
    int stride = gridDim.x * blockDim.x;
    for (; i < E; i += stride) atomicAdd(&lh[bucket_of(dist[i])], 1);
    __syncthreads();
    if (threadIdx.x < NBUCKETS) atomicAdd(&g_hist[threadIdx.x], lh[threadIdx.x]);
}

__global__ void k_scan() {
    if (threadIdx.x == 0 && blockIdx.x == 0) {
        int off = 0, goff = 0;
        for (int s = 0; s < NBUCKETS; s++) {
            int c = g_hist[s];
            g_start[s] = off; g_cursor[s] = off; g_count[s] = c;
            g_groupOff[s] = goff;
            off += c;
            goff += (c + G_TILES * 128 - 1) / (G_TILES * 128);
        }
        g_groupOff[NBUCKETS] = goff;
    }
}

__global__ void k_scatter(const float* __restrict__ dist, int E) {
    int lane = threadIdx.x & 31;
    unsigned ltmask = (1u << lane) - 1u;
    int i = blockIdx.x * blockDim.x + threadIdx.x;
    int stride = gridDim.x * blockDim.x;
    for (; i < E; i += stride) {
        int s = bucket_of(dist[i]);
        unsigned m = __match_any_sync(0xffffffffu, s);
        int leader = __ffs(m) - 1;
        int base = 0;
        if (lane == leader) base = atomicAdd(&g_cursor[s], __popc(m));
        base = __shfl_sync(0xffffffffu, base, leader);
        g_perm[base + __popc(m & ltmask)] = i;
    }
}

__global__ void k_wprep(const float* __restrict__ sel_w, const float* __restrict__ w1,
                        const float* __restrict__ w2, const float* __restrict__ w3,
                        const float* __restrict__ wout) {
    int slot = blockIdx.x;
    const float* src;
    bool tr;
    if (slot < 8) { src = sel_w + (size_t)slot * (H * H); tr = true; }
    else {
        const float* m[4] = {w1, w2, w3, wout};
        src = m[slot - 8]; tr = false;
    }
    for (int idx = threadIdx.x; idx < H * H; idx += blockDim.x) {
        int n = idx >> 7, k = idx & 127;
        float w = tr ? src[k * H + n] : src[n * H + k];
        if (slot < 8) {   // fp16 split
            __half hh = __float2half_rn(w);
            __half ll = __float2half_rn(w - __half2float(hh));
            g_wsp_hi[slot][n][k] = __half_as_ushort(hh);
            g_wsp_lo[slot][n][k] = __half_as_ushort(ll);
        } else {          // bf16 split
            __nv_bfloat16 hh = __float2bfloat16_rn(w);
            __nv_bfloat16 ll = __float2bfloat16_rn(w - __bfloat162float(hh));
            g_wsp_hi[slot][n][k] = __bfloat16_as_ushort(hh);
            g_wsp_lo[slot][n][k] = __bfloat16_as_ushort(ll);
        }
    }
}

// ---------------- kernel 5: grouped, pipelined edge expert GEMM (fp16 2-pass) ----------------
#define SM_META 0
#define SM_WT   32                          // 768 floats
#define SM_PERM (SM_WT + 3072)              // G*128 ints
#define SM_NODE (SM_PERM + 4096)
#define SM_RBF  (SM_NODE + 4096)            // 128*6 floats
#define SM_XBUF (SM_RBF + 3072 + 32)        // 128 rows x 512B
#define SM_AHI  (SM_XBUF + 65536)           // fp16 A (also reused as 64-row f32 D staging)
#define SM_BHI  (SM_AHI + 34816)
#define SM_BLO  (SM_BHI + 34816)
#define EDGE_SMEM_BYTES (SM_BLO + 34816)

__device__ __forceinline__ void issue_tile(const float* x, const float* rbf,
                                           const int* pt, uint32_t sbase, int t) {
    #pragma unroll 4
    for (int idx = t; idx < 4096; idx += THREADS) {
        int r = idx >> 5, seg = idx & 31;
        const char* src = (const char*)(x + (size_t)pt[r] * H) + seg * 16;
        CP16(sbase + SM_XBUF + r * 512 + seg * 16, src);
    }
    for (int idx = t; idx < 384; idx += THREADS) {
        int r = idx / 3, p = idx - r * 3;
        const char* src = (const char*)(rbf + (size_t)pt[r] * 6) + p * 8;
        CP8(sbase + SM_RBF + r * 24 + p * 8, src);
    }
}

__global__ void __launch_bounds__(THREADS, 1)
k_edge(const float* __restrict__ x, const float* __restrict__ rbf,
       const int* __restrict__ eidx, const float* __restrict__ w_rbf)
{
    extern __shared__ char sm[];
    int*   meta  = (int*)(sm + SM_META);
    float* sWT   = (float*)(sm + SM_WT);
    int*   permG = (int*)(sm + SM_PERM);
    int*   nodeG = (int*)(sm + SM_NODE);
    float* sRbf  = (float*)(sm + SM_RBF);
    uint32_t sbase = smem_u32(sm);

    int t = threadIdx.x, wid = t >> 5, lane = t & 31;

    if (t == 0) {
        int b = blockIdx.x;
        int found = -1, grpLocal = 0;
        if (b < g_groupOff[NBUCKETS]) {
            #pragma unroll
            for (int q = 0; q < NBUCKETS; q++)
                if (b >= g_groupOff[q] && b < g_groupOff[q + 1]) { found = q; grpLocal = b - g_groupOff[q]; }
        }
        if (found < 0) meta[0] = -1;
        else {
            int rowBase = grpLocal * (G_TILES * 128);
            int rem = g_count[found] - rowBase;
            if (rem > G_TILES * 128) rem = G_TILES * 128;
            meta[0] = found;
            meta[1] = (rem + 127) >> 7;
            meta[2] = g_start[found] + rowBase;
            meta[3] = rem;
        }
    }
    __syncthreads();
    int s = meta[0];
    if (s < 0) return;
    int nTiles = meta[1], rowStart = meta[2], rem = meta[3];

    for (int idx = t; idx < nTiles * 128; idx += THREADS)
        permG[idx] = (idx < rem) ? g_perm[rowStart + idx] : g_perm[rowStart];
    for (int idx = t; idx < 768; idx += THREADS) {
        int q = idx >> 7, c = idx & 127;
        sWT[idx] = w_rbf[c * 6 + q];
    }
    __syncthreads();
    for (int idx = t; idx < nTiles * 128; idx += THREADS)
        nodeG[idx] = eidx[permG[idx]];

    if (s < 8) {   // expert weight, once per group
        const char* srcH = (const char*)&g_wsp_hi[s][0][0];
        const char* srcL = (const char*)&g_wsp_lo[s][0][0];
        for (int i = t * 16; i < 34816; i += THREADS * 16) {
            CP16(sbase + SM_BHI + i, srcH + i);
            CP16(sbase + SM_BLO + i, srcL + i);
        }
    }
    issue_tile(x, rbf, permG, sbase, t);
    CP_COMMIT();
    CP_WAIT0();
    __syncthreads();

    int c0 = lane * 4;
    float4 wq[6];
    #pragma unroll
    for (int q = 0; q < 6; q++) wq[q] = *(float4*)&sWT[q * 128 + c0];

    int mi = wid & 3, nj = wid >> 2;
    int m0 = mi * 32, n0 = nj * 64;
    int m0b = wid * 16;                 // build mapping (16 rows per warp)
    float* sD = (float*)(sm + SM_AHI);  // 64-row f32 staging after MMA

    for (int i = 0; i < nTiles; i++) {
        int rows_i = min(128, rem - i * 128);
        const int* nodeT = nodeG + i * 128;

        // ---- build A(i): h = (rbf @ w_rbf^T) * x -> fp16 ----
        #pragma unroll 2
        for (int m = 0; m < 16; m++) {
            int r = m0b + m;
            bool act = (r < rows_i);
            const float* xr = (const float*)(sm + SM_XBUF + r * 512);
            float rq0 = sRbf[r * 6 + 0], rq1 = sRbf[r * 6 + 1], rq2 = sRbf[r * 6 + 2];
            float rq3 = sRbf[r * 6 + 3], rq4 = sRbf[r * 6 + 4], rq5 = sRbf[r * 6 + 5];
            float4 g;
            g.x = rq0*wq[0].x + rq1*wq[1].x + rq2*wq[2].x + rq3*wq[3].x + rq4*wq[4].x + rq5*wq[5].x;
            g.y = rq0*wq[0].y + rq1*wq[1].y + rq2*wq[2].y + rq3*wq[3].y + rq4*wq[4].y + rq5*wq[5].y;
            g.z = rq0*wq[0].z + rq1*wq[1].z + rq2*wq[2].z + rq3*wq[3].z + rq4*wq[4].z + rq5*wq[5].z;
            g.w = rq0*wq[0].w + rq1*wq[1].w + rq2*wq[2].w + rq3*wq[3].w + rq4*wq[4].w + rq5*wq[5].w;
            float4 xv = *(const float4*)&xr[c0];
            float h0 = act ? g.x * xv.x : 0.f;
            float h1 = act ? g.y * xv.y : 0.f;
            float h2 = act ? g.z * xv.z : 0.f;
            float h3 = act ? g.w * xv.w : 0.f;
            if (s < 8) {
                uint32_t off = (uint32_t)r * RSTRIDE_B + (uint32_t)c0 * 2;
                *(uint32_t*)(sm + SM_AHI + off)     = pack_half2(h0, h1);
                *(uint32_t*)(sm + SM_AHI + off + 4) = pack_half2(h2, h3);
            } else if (act) {
                red_add_v4((float*)g_accum4 + (size_t)nodeT[r] * H + c0, h0, h1, h2, h3);
            }
        }
        __syncthreads();

        // prefetch next tile while MMA runs (xbuf consumed by build above)
        if (i + 1 < nTiles) issue_tile(x, rbf, permG + (i + 1) * 128, sbase, t);
        CP_COMMIT();

        if (s < 8) {
            float acc[2][8][4];
            #pragma unroll
            for (int mt = 0; mt < 2; mt++)
                #pragma unroll
                for (int j = 0; j < 8; j++)
                    acc[mt][j][0] = acc[mt][j][1] = acc[mt][j][2] = acc[mt][j][3] = 0.f;

            mma_pass16(acc, sbase + SM_AHI, sbase + SM_BHI, lane, m0, n0);  // Ah*Bh
            mma_pass16(acc, sbase + SM_AHI, sbase + SM_BLO, lane, m0, n0);  // Ah*Bl
            __syncthreads();   // all ldsm done; A region reusable as D staging

            // ---- staged scatter, 64 rows per phase ----
            #pragma unroll
            for (int p = 0; p < 2; p++) {
                if ((m0 >> 6) == p) {
                    int lrBase = m0 - p * 64 + (lane >> 2);
                    int cBase = n0 + (lane & 3) * 2;
                    #pragma unroll
                    for (int mt = 0; mt < 2; mt++) {
                        #pragma unroll
                        for (int j = 0; j < 8; j++) {
                            int lr = lrBase + mt * 16;
                            int col = cBase + j * 8;
                            *(float2*)&sD[lr * SD_STRIDE + col] =
                                make_float2(acc[mt][j][0], acc[mt][j][1]);
                            *(float2*)&sD[(lr + 8) * SD_STRIDE + col] =
                                make_float2(acc[mt][j][2], acc[mt][j][3]);
                        }
                    }
                }
                __syncthreads();
                #pragma unroll 2
                for (int idx = t; idx < 2048; idx += THREADS) {
                    int row = p * 64 + (idx >> 5);
                    int c4 = (idx & 31) << 2;
                    if (row < rows_i) {
                        float4 v = *(float4*)&sD[(idx >> 5) * SD_STRIDE + c4];
                        red_add_v4((float*)g_accum4 + (size_t)nodeT[row] * H + c4,
                                   v.x, v.y, v.z, v.w);
                    }
                }
                __syncthreads();
            }
        }
        CP_WAIT0();
        __syncthreads();
    }
}

// ---------------- kernel 6: fused node MLP (bf16 3-pass, weights double-buffered) ----------------
#define MSM_BIAS 0
#define MSM_AHI  1536
#define MSM_ALO  (MSM_AHI + 34816)
#define MSM_W    (MSM_ALO + 34816)
#define MLP_SMEM_BYTES (MSM_W + 2 * 69632)

__device__ __forceinline__ void issue_weight(int slot, int buf, uint32_t sbase, int t) {
    const char* srcH = (const char*)&g_wsp_hi[slot][0][0];
    const char* srcL = (const char*)&g_wsp_lo[slot][0][0];
    uint32_t dst = sbase + MSM_W + (uint32_t)buf * 69632;
    for (int i = t * 16; i < 34816; i += THREADS * 16) {
        CP16(dst + i, srcH + i);
        CP16(dst + 34816 + i, srcL + i);
    }
}

__global__ void __launch_bounds__(THREADS, 1)
k_mlp(const float* __restrict__ b1, const float* __restrict__ b2,
      const float* __restrict__ b3, float* __restrict__ out, int N)
{
    extern __shared__ char sm[];
    float* sBias = (float*)(sm + MSM_BIAS);
    uint32_t sbase = smem_u32(sm);
    int t = threadIdx.x, wid = t >> 5, lane = t & 31;
    int nb = blockIdx.x * 128;
    int rows = min(128, N - nb);

    issue_weight(8, 0, sbase, t);
    CP_COMMIT();

    const float* accum = (const float*)g_accum4;
    for (int idx = t; idx < 128 * 32; idx += THREADS) {
        int r = idx >> 5, c4 = (idx & 31) * 4;
        float4 v = (r < rows) ? *(const float4*)&accum[(size_t)(nb + r) * H + c4]
                              : make_float4(0.f, 0.f, 0.f, 0.f);
        uint32_t lo0, lo1;
        uint32_t hi0 = split2_bf16(v.x, v.y, lo0);
        uint32_t hi1 = split2_bf16(v.z, v.w, lo1);
        uint32_t off = (uint32_t)r * RSTRIDE_B + (uint32_t)c4 * 2;
        *(uint32_t*)(sm + MSM_AHI + off)     = hi0;
        *(uint32_t*)(sm + MSM_AHI + off + 4) = hi1;
        *(uint32_t*)(sm + MSM_ALO + off)     = lo0;
        *(uint32_t*)(sm + MSM_ALO + off + 4) = lo1;
    }
    if (t < 128) {
        sBias[t]       = b1[t];
        sBias[t + 128] = b2[t];
        sBias[t + 256] = b3[t];
    }

    int m0 = wid * 16;
    int r0 = m0 + (lane >> 2), r1 = r0 + 8, cb = (lane & 3) * 2;

    for (int l = 0; l < 4; l++) {
        CP_WAIT0();
        __syncthreads();
        if (l < 3) { issue_weight(9 + l, (l + 1) & 1, sbase, t); CP_COMMIT(); }

        uint32_t wb = sbase + MSM_W + (uint32_t)(l & 1) * 69632;
        float acc[16][4];
        #pragma unroll
        for (int j = 0; j < 16; j++) { acc[j][0] = acc[j][1] = acc[j][2] = acc[j][3] = 0.f; }
        mma_stripe(acc, sbase + MSM_AHI, wb,         lane, m0);
        mma_stripe(acc, sbase + MSM_AHI, wb + 34816, lane, m0);
        mma_stripe(acc, sbase + MSM_ALO, wb,         lane, m0);
        __syncthreads();

        if (l < 3) {
            const float* bias = sBias + l * 128;
            #pragma unroll
            for (int j = 0; j < 16; j++) {
                int col = j * 8 + cb;
                float v0 = acc[j][0] + bias[col];
                float v1 = acc[j][1] + bias[col + 1];
                float v2 = acc[j][2] + bias[col];
                float v3 = acc[j][3] + bias[col + 1];
                v0 = v0 / (1.f + __expf(-v0));
                v1 = v1 / (1.f + __expf(-v1));
                v2 = v2 / (1.f + __expf(-v2));
                v3 = v3 / (1.f + __expf(-v3));
                uint32_t lo0, lo1;
                uint32_t hi0 = split2_bf16(v0, v1, lo0);
                uint32_t hi1 = split2_bf16(v2, v3, lo1);
                uint32_t off0 = (uint32_t)r0 * RSTRIDE_B + (uint32_t)col * 2;
                uint32_t off1 = (uint32_t)r1 * RSTRIDE_B + (uint32_t)col * 2;
                *(uint32_t*)(sm + MSM_AHI + off0) = hi0;
                *(uint32_t*)(sm + MSM_ALO + off0) = lo0;
                *(uint32_t*)(sm + MSM_AHI + off1) = hi1;
                *(uint32_t*)(sm + MSM_ALO + off1) = lo1;
            }
        } else {
            #pragma unroll
            for (int j = 0; j < 16; j++) {
                int col = j * 8 + cb;
                if (r0 < rows)
                    *(float2*)&out[(size_t)(nb + r0) * H + col] = make_float2(acc[j][0], acc[j][1]);
                if (r1 < rows)
                    *(float2*)&out[(size_t)(nb + r1) * H + col] = make_float2(acc[j][2], acc[j][3]);
            }
        }
    }
}

// ---------------- launcher ----------------
extern "C" void kernel_launch(void* const* d_in, const int* in_sizes, int n_in,
                              void* d_out, int out_size)
{
    const float* x    = (const float*)d_in[0];
    const float* rbf  = (const float*)d_in[1];
    const int*   ei   = (const int*)  d_in[2];
    const float* dist = (const float*)d_in[3];
    int k = 4;
    while (k < n_in && in_sizes[k] != 768) k++;
    const float* w_rbf = (const float*)d_in[k];
    const float* sel_w = (const float*)d_in[k + 1];
    const float* w1    = (const float*)d_in[k + 2];
    const float* b1    = (const float*)d_in[k + 3];
    const float* w2    = (const float*)d_in[k + 4];
    const float* b2    = (const float*)d_in[k + 5];
    const float* w3    = (const float*)d_in[k + 6];
    const float* b3    = (const float*)d_in[k + 7];
    const float* wout  = (const float*)d_in[k + 8];

    int E = in_sizes[0] / H;
    int N = out_size / H;

    cudaFuncSetAttribute(k_edge, cudaFuncAttributeMaxDynamicSharedMemorySize, EDGE_SMEM_BYTES);
    cudaFuncSetAttribute(k_mlp,  cudaFuncAttributeMaxDynamicSharedMemorySize, MLP_SMEM_BYTES);

    k_zero<<<512, 256>>>(N * (H / 4));
    k_hist<<<1024, 256>>>(dist, E);
    k_scan<<<1, 1>>>();
    k_scatter<<<1024, 256>>>(dist, E);
    k_wprep<<<12, 256>>>(sel_w, w1, w2, w3, wout);

    int maxGroups = (E + G_TILES * 128 - 1) / (G_TILES * 128) + NBUCKETS;
    k_edge<<<maxGroups, THREADS, EDGE_SMEM_BYTES>>>(x, rbf, ei, w_rbf);
    k_mlp<<<(N + 127) / 128, THREADS, MLP_SMEM_BYTES>>>(b1, b2, b3, (float*)d_out, N);
}

// round 6
// speedup vs baseline: 3.1587x; 1.0949x over previous
#include <cuda_runtime.h>
#include <cuda_bf16.h>
#include <cuda_fp16.h>
#include <cstdint>

#define H 128
#define NBUCKETS 9     // 8 expert buckets + 1 passthrough
#define THREADS 256
#define G_TILES 8      // tiles per CTA group (same bucket -> B amortized)

// row stride for 16-bit operand tiles: 136 elems = 272B = 17*16B (ldmatrix conflict-free)
#define RSTRIDE_E 136
#define RSTRIDE_B 272
#define SD_STRIDE 132  // f32 staging stride

// ---------------- device scratch ----------------
__device__ float4 g_accum4[100000 * (H / 4)];
__device__ int    g_perm[1000000];
__device__ int    g_hist[16];
__device__ int    g_start[NBUCKETS];
__device__ int    g_count[NBUCKETS];
__device__ int    g_cursor[NBUCKETS];
__device__ int    g_groupOff[NBUCKETS + 1];
// pre-converted weights: slots 0..7 experts (fp16, B^T[n][k]=W[k][n]),
// slots 8..11 = MLP w1,w2,w3,wout (bf16 hi/lo pairs, [n][k])
__device__ __align__(16) unsigned short g_wsp_hi[12][128][RSTRIDE_E];
__device__ __align__(16) unsigned short g_wsp_lo[12][128][RSTRIDE_E];

// ---------------- helpers ----------------
__device__ __forceinline__ int bucket_of(float d) {
    float t = (d - 0.8f) / 5.0001f * 8.0f;
    float f = floorf(t);
    return (f >= 0.0f && f < 8.0f) ? (int)f : 8;
}

__device__ __forceinline__ void red_add_v4(float* p, float a, float b, float c, float d) {
    asm volatile("red.global.add.v4.f32 [%0], {%1,%2,%3,%4};"
                 :: "l"(p), "f"(a), "f"(b), "f"(c), "f"(d) : "memory");
}

__device__ __forceinline__ uint32_t smem_u32(const void* p) {
    uint32_t a;
    asm("{ .reg .u64 t; cvta.to.shared.u64 t, %1; cvt.u32.u64 %0, t; }" : "=r"(a) : "l"(p));
    return a;
}

#define CP16(dst, src) asm volatile("cp.async.cg.shared.global [%0], [%1], 16;" :: "r"(dst), "l"(src))
#define CP8(dst, src)  asm volatile("cp.async.ca.shared.global [%0], [%1], 8;"  :: "r"(dst), "l"(src))
#define CP_COMMIT()    asm volatile("cp.async.commit_group;" ::: "memory")
#define CP_WAIT0()     asm volatile("cp.async.wait_group 0;" ::: "memory")

__device__ __forceinline__ void ldsm_x4(uint32_t& r0, uint32_t& r1, uint32_t& r2, uint32_t& r3,
                                        uint32_t addr) {
    asm volatile("ldmatrix.sync.aligned.m8n8.x4.shared.b16 {%0,%1,%2,%3}, [%4];"
                 : "=r"(r0), "=r"(r1), "=r"(r2), "=r"(r3) : "r"(addr));
}

__device__ __forceinline__ void mma_bf16(float* d, uint32_t a0, uint32_t a1, uint32_t a2,
                                         uint32_t a3, uint32_t b0, uint32_t b1) {
    asm volatile("mma.sync.aligned.m16n8k16.row.col.f32.bf16.bf16.f32 "
                 "{%0,%1,%2,%3}, {%4,%5,%6,%7}, {%8,%9}, {%0,%1,%2,%3};"
                 : "+f"(d[0]), "+f"(d[1]), "+f"(d[2]), "+f"(d[3])
                 : "r"(a0), "r"(a1), "r"(a2), "r"(a3), "r"(b0), "r"(b1));
}

__device__ __forceinline__ void mma_fp16(float* d, uint32_t a0, uint32_t a1, uint32_t a2,
                                         uint32_t a3, uint32_t b0, uint32_t b1) {
    asm volatile("mma.sync.aligned.m16n8k16.row.col.f32.f16.f16.f32 "
                 "{%0,%1,%2,%3}, {%4,%5,%6,%7}, {%8,%9}, {%0,%1,%2,%3};"
                 : "+f"(d[0]), "+f"(d[1]), "+f"(d[2]), "+f"(d[3])
                 : "r"(a0), "r"(a1), "r"(a2), "r"(a3), "r"(b0), "r"(b1));
}

__device__ __forceinline__ uint32_t split2_bf16(float v0, float v1, uint32_t& lo) {
    __nv_bfloat16 h0 = __float2bfloat16_rn(v0), h1 = __float2bfloat16_rn(v1);
    __nv_bfloat16 l0 = __float2bfloat16_rn(v0 - __bfloat162float(h0));
    __nv_bfloat16 l1 = __float2bfloat16_rn(v1 - __bfloat162float(h1));
    lo = (uint32_t)__bfloat16_as_ushort(l0) | ((uint32_t)__bfloat16_as_ushort(l1) << 16);
    return (uint32_t)__bfloat16_as_ushort(h0) | ((uint32_t)__bfloat16_as_ushort(h1) << 16);
}

__device__ __forceinline__ uint32_t pack_half2(float v0, float v1) {
    __half h0 = __float2half_rn(v0), h1 = __float2half_rn(v1);
    return (uint32_t)__half_as_ushort(h0) | ((uint32_t)__half_as_ushort(h1) << 16);
}

// bf16 split pass for k_mlp: acc[16][4] += A(16x128 stripe at m0) * B^T(128x128)
__device__ __forceinline__ void mma_stripe(float (*acc)[4], uint32_t aBase, uint32_t bBase,
                                           int lane, int m0) {
    uint32_t aAddr = aBase + (uint32_t)(m0 + (lane & 15)) * RSTRIDE_B
                   + (uint32_t)((lane >> 4) << 4);
    uint32_t bAddr = bBase + (uint32_t)((lane & 7) + ((lane >> 4) << 3)) * RSTRIDE_B
                   + (uint32_t)(((lane >> 3) & 1) << 4);
    #pragma unroll
    for (int k0 = 0; k0 < 8; k0++) {
        uint32_t a0, a1, a2, a3;
        ldsm_x4(a0, a1, a2, a3, aAddr + k0 * 32);
        #pragma unroll
        for (int j2 = 0; j2 < 8; j2++) {
            uint32_t b0, b1, b2, b3;
            ldsm_x4(b0, b1, b2, b3, bAddr + j2 * (16 * RSTRIDE_B) + k0 * 32);
            mma_bf16(acc[j2 * 2],     a0, a1, a2, a3, b0, b1);
            mma_bf16(acc[j2 * 2 + 1], a0, a1, a2, a3, b2, b3);
        }
    }
}

// fp16 pass for k_edge: acc[2][8][4] += A(32x128 at m0) * B^T(64 cols at n0)
__device__ __forceinline__ void mma_pass16(float (*acc)[8][4], uint32_t aBase, uint32_t bBase,
                                           int lane, int m0, int n0) {
    uint32_t aAddr = aBase + (uint32_t)(m0 + (lane & 15)) * RSTRIDE_B
                   + (uint32_t)((lane >> 4) << 4);
    uint32_t bAddr = bBase + (uint32_t)(n0 + (lane & 7) + ((lane >> 4) << 3)) * RSTRIDE_B
                   + (uint32_t)(((lane >> 3) & 1) << 4);
    #pragma unroll
    for (int k0 = 0; k0 < 8; k0++) {
        uint32_t a0, a1, a2, a3, c0, c1, c2, c3;
        ldsm_x4(a0, a1, a2, a3, aAddr + k0 * 32);
        ldsm_x4(c0, c1, c2, c3, aAddr + 16 * RSTRIDE_B + k0 * 32);
        #pragma unroll
        for (int j2 = 0; j2 < 4; j2++) {
            uint32_t b0, b1, b2, b3;
            ldsm_x4(b0, b1, b2, b3, bAddr + j2 * (16 * RSTRIDE_B) + k0 * 32);
            mma_fp16(acc[0][j2 * 2],     a0, a1, a2, a3, b0, b1);
            mma_fp16(acc[0][j2 * 2 + 1], a0, a1, a2, a3, b2, b3);
            mma_fp16(acc[1][j2 * 2],     c0, c1, c2, c3, b0, b1);
            mma_fp16(acc[1][j2 * 2 + 1], c0, c1, c2, c3, b2, b3);
        }
    }
}

// ---------------- small kernels ----------------
__global__ void k_zero(int n4) {
    int i = blockIdx.x * blockDim.x + threadIdx.x;
    int stride = gridDim.x * blockDim.x;
    float4 z = make_float4(0.f, 0.f, 0.f, 0.f);
    for (; i < n4; i += stride) g_accum4[i] = z;
    if (blockIdx.x == 0 && threadIdx.x < 16) g_hist[threadIdx.x] = 0;
}

__global__ void k_hist(const float* __restrict__ dist, int E) {
    __shared__ int lh[NBUCKETS];
    if (threadIdx.x < NBUCKETS) lh[threadIdx.x] = 0;
    __syncthreads();
    int i = blockIdx.x * blockDim.x + threadIdx.x;
    int stride = gridDim.x * blockDim.x;
    for (; i < E; i += stride) atomicAdd(&lh[bucket_of(dist[i])], 1);
    __syncthreads();
    if (threadIdx.x < NBUCKETS) atomicAdd(&g_hist[threadIdx.x], lh[threadIdx.x]);
}

__global__ void k_scan() {
    if (threadIdx.x == 0 && blockIdx.x == 0) {
        int off = 0, goff = 0;
        for (int s = 0; s < NBUCKETS; s++) {
            int c = g_hist[s];
            g_start[s] = off; g_cursor[s] = off; g_count[s] = c;
            g_groupOff[s] = goff;
            off += c;
            goff += (c + G_TILES * 128 - 1) / (G_TILES * 128);
        }
        g_groupOff[NBUCKETS] = goff;
    }
}

__global__ void k_scatter(const float* __restrict__ dist, int E) {
    int lane = threadIdx.x & 31;
    unsigned ltmask = (1u << lane) - 1u;
    int i = blockIdx.x * blockDim.x + threadIdx.x;
    int stride = gridDim.x * blockDim.x;
    for (; i < E; i += stride) {
        int s = bucket_of(dist[i]);
        unsigned m = __match_any_sync(0xffffffffu, s);
        int leader = __ffs(m) - 1;
        int base = 0;
        if (lane == leader) base = atomicAdd(&g_cursor[s], __popc(m));
        base = __shfl_sync(0xffffffffu, base, leader);
        g_perm[base + __popc(m & ltmask)] = i;
    }
}

__global__ void k_wprep(const float* __restrict__ sel_w, const float* __restrict__ w1,
                        const float* __restrict__ w2, const float* __restrict__ w3,
                        const float* __restrict__ wout) {
    int slot = blockIdx.x;
    const float* src;
    bool tr;
    if (slot < 8) { src = sel_w + (size_t)slot * (H * H); tr = true; }
    else {
        const float* m[4] = {w1, w2, w3, wout};
        src = m[slot - 8]; tr = false;
    }
    for (int idx = threadIdx.x; idx < H * H; idx += blockDim.x) {
        int n = idx >> 7, k = idx & 127;
        float w = tr ? src[k * H + n] : src[n * H + k];
        if (slot < 8) {   // plain fp16 (single-pass MMA)
            g_wsp_hi[slot][n][k] = __half_as_ushort(__float2half_rn(w));
            g_wsp_lo[slot][n][k] = 0;
        } else {          // bf16 split-2 for MLP
            __nv_bfloat16 hh = __float2bfloat16_rn(w);
            __nv_bfloat16 ll = __float2bfloat16_rn(w - __bfloat162float(hh));
            g_wsp_hi[slot][n][k] = __bfloat16_as_ushort(hh);
            g_wsp_lo[slot][n][k] = __bfloat16_as_ushort(ll);
        }
    }
}

// ---------------- kernel 5: grouped, pipelined edge expert GEMM (fp16 single-pass) ----------------
#define SM_META 0
#define SM_WT   32                          // 768 floats
#define SM_PERM (SM_WT + 3072)              // G*128 ints
#define SM_NODE (SM_PERM + 4096)
#define SM_RBF  (SM_NODE + 4096)            // 128*6 floats
#define SM_XBUF (SM_RBF + 3072 + 32)        // 128 rows x 512B
#define SM_AHI  (SM_XBUF + 65536)           // fp16 A tile
#define SM_BHI  (SM_AHI + 34816)            // fp16 B tile
#define SM_DST  (SM_BHI + 34816)            // f32 D staging, 128 x SD_STRIDE
#define EDGE_SMEM_BYTES (SM_DST + 128 * SD_STRIDE * 4)

__device__ __forceinline__ void issue_tile(const float* x, const float* rbf,
                                           const int* pt, uint32_t sbase, int t) {
    #pragma unroll 4
    for (int idx = t; idx < 4096; idx += THREADS) {
        int r = idx >> 5, seg = idx & 31;
        const char* src = (const char*)(x + (size_t)pt[r] * H) + seg * 16;
        CP16(sbase + SM_XBUF + r * 512 + seg * 16, src);
    }
    for (int idx = t; idx < 384; idx += THREADS) {
        int r = idx / 3, p = idx - r * 3;
        const char* src = (const char*)(rbf + (size_t)pt[r] * 6) + p * 8;
        CP8(sbase + SM_RBF + r * 24 + p * 8, src);
    }
}

__global__ void __launch_bounds__(THREADS, 1)
k_edge(const float* __restrict__ x, const float* __restrict__ rbf,
       const int* __restrict__ eidx, const float* __restrict__ w_rbf)
{
    extern __shared__ char sm[];
    int*   meta  = (int*)(sm + SM_META);
    float* sWT   = (float*)(sm + SM_WT);
    int*   permG = (int*)(sm + SM_PERM);
    int*   nodeG = (int*)(sm + SM_NODE);
    float* sRbf  = (float*)(sm + SM_RBF);
    float* sD    = (float*)(sm + SM_DST);
    uint32_t sbase = smem_u32(sm);

    int t = threadIdx.x, wid = t >> 5, lane = t & 31;

    if (t == 0) {
        int b = blockIdx.x;
        int found = -1, grpLocal = 0;
        if (b < g_groupOff[NBUCKETS]) {
            #pragma unroll
            for (int q = 0; q < NBUCKETS; q++)
                if (b >= g_groupOff[q] && b < g_groupOff[q + 1]) { found = q; grpLocal = b - g_groupOff[q]; }
        }
        if (found < 0) meta[0] = -1;
        else {
            int rowBase = grpLocal * (G_TILES * 128);
            int rem = g_count[found] - rowBase;
            if (rem > G_TILES * 128) rem = G_TILES * 128;
            meta[0] = found;
            meta[1] = (rem + 127) >> 7;
            meta[2] = g_start[found] + rowBase;
            meta[3] = rem;
        }
    }
    __syncthreads();
    int s = meta[0];
    if (s < 0) return;
    int nTiles = meta[1], rowStart = meta[2], rem = meta[3];

    for (int idx = t; idx < nTiles * 128; idx += THREADS)
        permG[idx] = (idx < rem) ? g_perm[rowStart + idx] : g_perm[rowStart];
    for (int idx = t; idx < 768; idx += THREADS) {
        int q = idx >> 7, c = idx & 127;
        sWT[idx] = w_rbf[c * 6 + q];
    }
    __syncthreads();
    for (int idx = t; idx < nTiles * 128; idx += THREADS)
        nodeG[idx] = eidx[permG[idx]];

    if (s < 8) {   // expert weight (fp16), once per group
        const char* srcH = (const char*)&g_wsp_hi[s][0][0];
        for (int i = t * 16; i < 34816; i += THREADS * 16)
            CP16(sbase + SM_BHI + i, srcH + i);
    }
    issue_tile(x, rbf, permG, sbase, t);
    CP_COMMIT();
    CP_WAIT0();
    __syncthreads();

    int c0 = lane * 4;
    float4 wq[6];
    #pragma unroll
    for (int q = 0; q < 6; q++) wq[q] = *(float4*)&sWT[q * 128 + c0];

    int mi = wid & 3, nj = wid >> 2;
    int m0 = mi * 32, n0 = nj * 64;
    int m0b = wid * 16;                 // build mapping (16 rows per warp)

    for (int i = 0; i < nTiles; i++) {
        int rows_i = min(128, rem - i * 128);
        const int* nodeT = nodeG + i * 128;

        // ---- build A(i): h = (rbf @ w_rbf^T) * x -> fp16 ----
        #pragma unroll 2
        for (int m = 0; m < 16; m++) {
            int r = m0b + m;
            bool act = (r < rows_i);
            const float* xr = (const float*)(sm + SM_XBUF + r * 512);
            float rq0 = sRbf[r * 6 + 0], rq1 = sRbf[r * 6 + 1], rq2 = sRbf[r * 6 + 2];
            float rq3 = sRbf[r * 6 + 3], rq4 = sRbf[r * 6 + 4], rq5 = sRbf[r * 6 + 5];
            float4 g;
            g.x = rq0*wq[0].x + rq1*wq[1].x + rq2*wq[2].x + rq3*wq[3].x + rq4*wq[4].x + rq5*wq[5].x;
            g.y = rq0*wq[0].y + rq1*wq[1].y + rq2*wq[2].y + rq3*wq[3].y + rq4*wq[4].y + rq5*wq[5].y;
            g.z = rq0*wq[0].z + rq1*wq[1].z + rq2*wq[2].z + rq3*wq[3].z + rq4*wq[4].z + rq5*wq[5].z;
            g.w = rq0*wq[0].w + rq1*wq[1].w + rq2*wq[2].w + rq3*wq[3].w + rq4*wq[4].w + rq5*wq[5].w;
            float4 xv = *(const float4*)&xr[c0];
            float h0 = act ? g.x * xv.x : 0.f;
            float h1 = act ? g.y * xv.y : 0.f;
            float h2 = act ? g.z * xv.z : 0.f;
            float h3 = act ? g.w * xv.w : 0.f;
            if (s < 8) {
                uint32_t off = (uint32_t)r * RSTRIDE_B + (uint32_t)c0 * 2;
                *(uint32_t*)(sm + SM_AHI + off)     = pack_half2(h0, h1);
                *(uint32_t*)(sm + SM_AHI + off + 4) = pack_half2(h2, h3);
            } else if (act) {
                red_add_v4((float*)g_accum4 + (size_t)nodeT[r] * H + c0, h0, h1, h2, h3);
            }
        }
        __syncthreads();

        // prefetch next tile while MMA runs
        if (i + 1 < nTiles) issue_tile(x, rbf, permG + (i + 1) * 128, sbase, t);
        CP_COMMIT();

        if (s < 8) {
            float acc[2][8][4];
            #pragma unroll
            for (int mt = 0; mt < 2; mt++)
                #pragma unroll
                for (int j = 0; j < 8; j++)
                    acc[mt][j][0] = acc[mt][j][1] = acc[mt][j][2] = acc[mt][j][3] = 0.f;

            mma_pass16(acc, sbase + SM_AHI, sbase + SM_BHI, lane, m0, n0);  // single pass

            // ---- stage D (own region per warp; no pre-sync needed) ----
            int lrBase = m0 + (lane >> 2);
            int cBase = n0 + (lane & 3) * 2;
            #pragma unroll
            for (int mt = 0; mt < 2; mt++) {
                #pragma unroll
                for (int j = 0; j < 8; j++) {
                    int lr = lrBase + mt * 16;
                    int col = cBase + j * 8;
                    *(float2*)&sD[lr * SD_STRIDE + col] =
                        make_float2(acc[mt][j][0], acc[mt][j][1]);
                    *(float2*)&sD[(lr + 8) * SD_STRIDE + col] =
                        make_float2(acc[mt][j][2], acc[mt][j][3]);
                }
            }
            __syncthreads();

            // ---- single-phase red.v4 scatter of all 128 rows ----
            #pragma unroll 4
            for (int idx = t; idx < 4096; idx += THREADS) {
                int row = idx >> 5, c4 = (idx & 31) << 2;
                if (row < rows_i) {
                    float4 v = *(float4*)&sD[row * SD_STRIDE + c4];
                    red_add_v4((float*)g_accum4 + (size_t)nodeT[row] * H + c4,
                               v.x, v.y, v.z, v.w);
                }
            }
        }
        CP_WAIT0();
        __syncthreads();
    }
}

// ---------------- kernel 6: fused node MLP (bf16 3-pass, weights double-buffered) ----------------
#define MSM_BIAS 0
#define MSM_AHI  1536
#define MSM_ALO  (MSM_AHI + 34816)
#define MSM_W    (MSM_ALO + 34816)
#define MLP_SMEM_BYTES (MSM_W + 2 * 69632)

__device__ __forceinline__ void issue_weight(int slot, int buf, uint32_t sbase, int t) {
    const char* srcH = (const char*)&g_wsp_hi[slot][0][0];
    const char* srcL = (const char*)&g_wsp_lo[slot][0][0];
    uint32_t dst = sbase + MSM_W + (uint32_t)buf * 69632;
    for (int i = t * 16; i < 34816; i += THREADS * 16) {
        CP16(dst + i, srcH + i);
        CP16(dst + 34816 + i, srcL + i);
    }
}

__global__ void __launch_bounds__(THREADS, 1)
k_mlp(const float* __restrict__ b1, const float* __restrict__ b2,
      const float* __restrict__ b3, float* __restrict__ out, int N)
{
    extern __shared__ char sm[];
    float* sBias = (float*)(sm + MSM_BIAS);
    uint32_t sbase = smem_u32(sm);
    int t = threadIdx.x, wid = t >> 5, lane = t & 31;
    int nb = blockIdx.x * 128;
    int rows = min(128, N - nb);

    issue_weight(8, 0, sbase, t);
    CP_COMMIT();

    const float* accum = (const float*)g_accum4;
    for (int idx = t; idx < 128 * 32; idx += THREADS) {
        int r = idx >> 5, c4 = (idx & 31) * 4;
        float4 v = (r < rows) ? *(const float4*)&accum[(size_t)(nb + r) * H + c4]
                              : make_float4(0.f, 0.f, 0.f, 0.f);
        uint32_t lo0, lo1;
        uint32_t hi0 = split2_bf16(v.x, v.y, lo0);
        uint32_t hi1 = split2_bf16(v.z, v.w, lo1);
        uint32_t off = (uint32_t)r * RSTRIDE_B + (uint32_t)c4 * 2;
        *(uint32_t*)(sm + MSM_AHI + off)     = hi0;
        *(uint32_t*)(sm + MSM_AHI + off + 4) = hi1;
        *(uint32_t*)(sm + MSM_ALO + off)     = lo0;
        *(uint32_t*)(sm + MSM_ALO + off + 4) = lo1;
    }
    if (t < 128) {
        sBias[t]       = b1[t];
        sBias[t + 128] = b2[t];
        sBias[t + 256] = b3[t];
    }

    int m0 = wid * 16;
    int r0 = m0 + (lane >> 2), r1 = r0 + 8, cb = (lane & 3) * 2;

    for (int l = 0; l < 4; l++) {
        CP_WAIT0();
        __syncthreads();
        if (l < 3) { issue_weight(9 + l, (l + 1) & 1, sbase, t); CP_COMMIT(); }

        uint32_t wb = sbase + MSM_W + (uint32_t)(l & 1) * 69632;
        float acc[16][4];
        #pragma unroll
        for (int j = 0; j < 16; j++) { acc[j][0] = acc[j][1] = acc[j][2] = acc[j][3] = 0.f; }
        mma_stripe(acc, sbase + MSM_AHI, wb,         lane, m0);
        mma_stripe(acc, sbase + MSM_AHI, wb + 34816, lane, m0);
        mma_stripe(acc, sbase + MSM_ALO, wb,         lane, m0);
        __syncthreads();

        if (l < 3) {
            const float* bias = sBias + l * 128;
            #pragma unroll
            for (int j = 0; j < 16; j++) {
                int col = j * 8 + cb;
                float v0 = acc[j][0] + bias[col];
                float v1 = acc[j][1] + bias[col + 1];
                float v2 = acc[j][2] + bias[col];
                float v3 = acc[j][3] + bias[col + 1];
                v0 = v0 / (1.f + __expf(-v0));
                v1 = v1 / (1.f + __expf(-v1));
                v2 = v2 / (1.f + __expf(-v2));
                v3 = v3 / (1.f + __expf(-v3));
                uint32_t lo0, lo1;
                uint32_t hi0 = split2_bf16(v0, v1, lo0);
                uint32_t hi1 = split2_bf16(v2, v3, lo1);
                uint32_t off0 = (uint32_t)r0 * RSTRIDE_B + (uint32_t)col * 2;
                uint32_t off1 = (uint32_t)r1 * RSTRIDE_B + (uint32_t)col * 2;
                *(uint32_t*)(sm + MSM_AHI + off0) = hi0;
                *(uint32_t*)(sm + MSM_ALO + off0) = lo0;
                *(uint32_t*)(sm + MSM_AHI + off1) = hi1;
                *(uint32_t*)(sm + MSM_ALO + off1) = lo1;
            }
        } else {
            #pragma unroll
            for (int j = 0; j < 16; j++) {
                int col = j * 8 + cb;
                if (r0 < rows)
                    *(float2*)&out[(size_t)(nb + r0) * H + col] = make_float2(acc[j][0], acc[j][1]);
                if (r1 < rows)
                    *(float2*)&out[(size_t)(nb + r1) * H + col] = make_float2(acc[j][2], acc[j][3]);
            }
        }
    }
}

// ---------------- launcher ----------------
extern "C" void kernel_launch(void* const* d_in, const int* in_sizes, int n_in,
                              void* d_out, int out_size)
{
    const float* x    = (const float*)d_in[0];
    const float* rbf  = (const float*)d_in[1];
    const int*   ei   = (const int*)  d_in[2];
    const float* dist = (const float*)d_in[3];
    int k = 4;
    while (k < n_in && in_sizes[k] != 768) k++;
    const float* w_rbf = (const float*)d_in[k];
    const float* sel_w = (const float*)d_in[k + 1];
    const float* w1    = (const float*)d_in[k + 2];
    const float* b1    = (const float*)d_in[k + 3];
    const float* w2    = (const float*)d_in[k + 4];
    const float* b2    = (const float*)d_in[k + 5];
    const float* w3    = (const float*)d_in[k + 6];
    const float* b3    = (const float*)d_in[k + 7];
    const float* wout  = (const float*)d_in[k + 8];

    int E = in_sizes[0] / H;
    int N = out_size / H;

    cudaFuncSetAttribute(k_edge, cudaFuncAttributeMaxDynamicSharedMemorySize, EDGE_SMEM_BYTES);
    cudaFuncSetAttribute(k_mlp,  cudaFuncAttributeMaxDynamicSharedMemorySize, MLP_SMEM_BYTES);

    k_zero<<<512, 256>>>(N * (H / 4));
    k_hist<<<1024, 256>>>(dist, E);
    k_scan<<<1, 1>>>();
    k_scatter<<<1024, 256>>>(dist, E);
    k_wprep<<<12, 256>>>(sel_w, w1, w2, w3, wout);

    int maxGroups = (E + G_TILES * 128 - 1) / (G_TILES * 128) + NBUCKETS;
    k_edge<<<maxGroups, THREADS, EDGE_SMEM_BYTES>>>(x, rbf, ei, w_rbf);
    k_mlp<<<(N + 127) / 128, THREADS, MLP_SMEM_BYTES>>>(b1, b2, b3, (float*)d_out, N);
}